// round 1
// baseline (speedup 1.0000x reference)
#include <cuda_runtime.h>
#include <math.h>

#define BB 16
#define LL 2048
#define DD 256
#define HH 8
#define HDIM 32
#define KWIN 7
#define NDEPTH 2
#define LOUT 1024
#define OCH 512
#define KCONV 768          // 256 * 3
#define NTOK (BB*LL)       // 32768
#define Y_ELEMS (BB*LOUT*OCH) // 8388608

// ---------------- scratch (no allocs allowed) ----------------
__device__ float g_t0  [(size_t)NTOK*DD];        // LN output
__device__ float g_qkv [(size_t)NTOK*3*DD];      // qkv
__device__ float g_attn[(size_t)NTOK*DD];        // attention out
__device__ float g_hid [(size_t)NTOK*4*DD];      // MLP hidden
__device__ float g_col [(size_t)BB*LOUT*KCONV];  // im2col
__device__ float g_wT  [(size_t)KCONV*OCH];      // transposed conv weight
__device__ float g_conv[(size_t)BB*LOUT*OCH];    // conv output pre-LN

// ---------------- helpers ----------------
__device__ __forceinline__ float blockReduceSum(float v) {
    __shared__ float s[8];
    int lane = threadIdx.x & 31, w = threadIdx.x >> 5;
    #pragma unroll
    for (int o = 16; o; o >>= 1) v += __shfl_xor_sync(0xffffffffu, v, o);
    if (lane == 0) s[w] = v;
    __syncthreads();
    if (w == 0) {
        v = (lane < 8) ? s[lane] : 0.0f;
        #pragma unroll
        for (int o = 4; o; o >>= 1) v += __shfl_xor_sync(0xffffffffu, v, o);
        if (lane == 0) s[0] = v;
    }
    __syncthreads();
    float r = s[0];
    __syncthreads();
    return r;
}

// ---------------- elementwise kernels ----------------
__global__ void copy4_kernel(const float4* __restrict__ src, float4* __restrict__ dst, int n4) {
    int i = blockIdx.x * blockDim.x + threadIdx.x;
    if (i < n4) dst[i] = src[i];
}

// LayerNorm over last dim W (256 or 512); one block (256 thr) per row
__global__ void ln_kernel(const float* __restrict__ x, const float* __restrict__ g,
                          const float* __restrict__ bta, float* __restrict__ out, int W) {
    int row = blockIdx.x;
    const float* xr = x + (size_t)row * W;
    float* orow = out + (size_t)row * W;
    int n = W >> 8;                  // elems per thread: 1 (W=256) or 2 (W=512)
    float e[2];
    float sum = 0.f;
    for (int i = 0; i < n; i++) { e[i] = xr[threadIdx.x + (i << 8)]; sum += e[i]; }
    float m = blockReduceSum(sum) / (float)W;
    float sq = 0.f;
    for (int i = 0; i < n; i++) { float d = e[i] - m; sq += d * d; }
    float var = blockReduceSum(sq) / (float)W;
    float r = rsqrtf(var + 1e-5f);
    for (int i = 0; i < n; i++) {
        int c = threadIdx.x + (i << 8);
        orow[c] = (e[i] - m) * r * g[c] + bta[c];
    }
}

// Neighborhood attention: one warp per (b, l, h); lane = head-dim element
__global__ void nat_attn_kernel(const float* __restrict__ qkv, float* __restrict__ out) {
    int warp = blockIdx.x * (blockDim.x >> 5) + (threadIdx.x >> 5);
    int lane = threadIdx.x & 31;
    int h = warp & (HH - 1);
    int token = warp >> 3;           // b*LL + l
    int l = token & (LL - 1);
    int b = token >> 11;
    const float SCALE = 0.17677669529663687f; // 32^-0.5
    float q = qkv[(size_t)token * 768 + h * HDIM + lane] * SCALE;
    int start = l - (KWIN / 2);
    if (start < 0) start = 0;
    if (start > LL - KWIN) start = LL - KWIN;
    float s[KWIN], v[KWIN];
    size_t basebl = (size_t)(b * LL) * 768;
    #pragma unroll
    for (int j = 0; j < KWIN; j++) {
        size_t off = basebl + (size_t)(start + j) * 768 + h * HDIM + lane;
        float kk = qkv[off + 256];
        v[j]     = qkv[off + 512];
        float p = q * kk;
        #pragma unroll
        for (int o = 16; o; o >>= 1) p += __shfl_xor_sync(0xffffffffu, p, o);
        s[j] = p;
    }
    float mx = s[0];
    #pragma unroll
    for (int j = 1; j < KWIN; j++) mx = fmaxf(mx, s[j]);
    float sum = 0.f;
    #pragma unroll
    for (int j = 0; j < KWIN; j++) { s[j] = __expf(s[j] - mx); sum += s[j]; }
    float inv = 1.0f / sum;
    float o = 0.f;
    #pragma unroll
    for (int j = 0; j < KWIN; j++) o += s[j] * v[j];
    out[(size_t)token * DD + h * HDIM + lane] = o * inv;
}

// conv_w [OCH][256][3] -> wT [KCONV][OCH], kk = ic*3+kh
__global__ void wtrans_kernel(const float* __restrict__ w, float* __restrict__ wT) {
    int i = blockIdx.x * blockDim.x + threadIdx.x;
    if (i >= KCONV * OCH) return;
    int oc = i % OCH;
    int kk = i / OCH;
    wT[i] = w[(size_t)oc * KCONV + kk];
}

// im2col for stride-2, pad-1, kw=3 conv over x [B, L, D]
__global__ void im2col_kernel(const float* __restrict__ x, float* __restrict__ col) {
    size_t i = (size_t)blockIdx.x * blockDim.x + threadIdx.x;
    if (i >= (size_t)BB * LOUT * KCONV) return;
    int kk = (int)(i % KCONV);
    size_t m = i / KCONV;
    int lo = (int)(m % LOUT);
    int b  = (int)(m / LOUT);
    int ic = kk / 3, kh = kk % 3;
    int t = 2 * lo - 1 + kh;
    float val = 0.f;
    if (t >= 0 && t < LL) val = x[((size_t)(b * LL + t)) * DD + ic];
    col[i] = val;
}

// ---------------- generic tiled fp32 GEMM ----------------
// C[M,N] = A[M,K] @ B[K,N]  (+ bias / gelu / residual per EPI)
// 64x64 tile, BK=16, 256 threads, 4x4 per thread
#define EPI_NONE      0
#define EPI_BIAS      1
#define EPI_BIAS_GELU 2
#define EPI_BIAS_RES  3

template <int EPI>
__global__ void __launch_bounds__(256) gemm64(
    const float* __restrict__ A, const float* __restrict__ Bm,
    const float* __restrict__ bias, const float* __restrict__ res,
    float* __restrict__ C, int M, int N, int K)
{
    __shared__ float As[16][64];
    __shared__ float Bs[16][64];
    int tid = threadIdx.x;
    int tx = tid & 15, ty = tid >> 4;
    int m0 = blockIdx.y * 64, n0 = blockIdx.x * 64;
    float acc[4][4] = {};
    int arow = tid >> 2, acol4 = (tid & 3) * 4;
    int brow = tid >> 4, bcol = (tid & 15) * 4;
    for (int k0 = 0; k0 < K; k0 += 16) {
        float4 a = *(const float4*)&A[(size_t)(m0 + arow) * K + k0 + acol4];
        As[acol4 + 0][arow] = a.x;
        As[acol4 + 1][arow] = a.y;
        As[acol4 + 2][arow] = a.z;
        As[acol4 + 3][arow] = a.w;
        *(float4*)&Bs[brow][bcol] = *(const float4*)&Bm[(size_t)(k0 + brow) * N + n0 + bcol];
        __syncthreads();
        #pragma unroll
        for (int k = 0; k < 16; k++) {
            float4 ra = *(const float4*)&As[k][ty << 2];
            float4 rb = *(const float4*)&Bs[k][tx << 2];
            float av[4] = {ra.x, ra.y, ra.z, ra.w};
            float bv[4] = {rb.x, rb.y, rb.z, rb.w};
            #pragma unroll
            for (int i = 0; i < 4; i++)
                #pragma unroll
                for (int j = 0; j < 4; j++)
                    acc[i][j] = fmaf(av[i], bv[j], acc[i][j]);
        }
        __syncthreads();
    }
    #pragma unroll
    for (int i = 0; i < 4; i++) {
        int m = m0 + (ty << 2) + i;
        #pragma unroll
        for (int j = 0; j < 4; j++) {
            int n = n0 + (tx << 2) + j;
            float v = acc[i][j];
            if (EPI >= 1) v += bias[n];
            if (EPI == EPI_BIAS_GELU)
                v = 0.5f * v * (1.0f + erff(v * 0.70710678118654752f));
            if (EPI == EPI_BIAS_RES)
                v += res[(size_t)m * N + n];
            C[(size_t)m * N + n] = v;
        }
    }
}

// ---------------- launch ----------------
extern "C" void kernel_launch(void* const* d_in, const int* in_sizes, int n_in,
                              void* d_out, int out_size)
{
    const float* x_in   = (const float*)d_in[0];
    const float* ln1_g  = (const float*)d_in[1];
    const float* ln1_b  = (const float*)d_in[2];
    const float* qkv_w  = (const float*)d_in[3];
    const float* qkv_b  = (const float*)d_in[4];
    const float* proj_w = (const float*)d_in[5];
    const float* proj_b = (const float*)d_in[6];
    const float* ln2_g  = (const float*)d_in[7];
    const float* ln2_b  = (const float*)d_in[8];
    const float* fc1_w  = (const float*)d_in[9];
    const float* fc1_b  = (const float*)d_in[10];
    const float* fc2_w  = (const float*)d_in[11];
    const float* fc2_b  = (const float*)d_in[12];
    const float* conv_w = (const float*)d_in[13];
    const float* dn_g   = (const float*)d_in[14];
    const float* dn_b   = (const float*)d_in[15];

    float* y_out = (float*)d_out;           // [B, 1024, 512]
    float* xbuf  = y_out + Y_ELEMS;         // [B, 2048, 256] residual stream lives in d_out

    void* p;
    float *t0, *qkv, *attn, *hid, *col, *wT, *conv;
    cudaGetSymbolAddress(&p, g_t0);   t0   = (float*)p;
    cudaGetSymbolAddress(&p, g_qkv);  qkv  = (float*)p;
    cudaGetSymbolAddress(&p, g_attn); attn = (float*)p;
    cudaGetSymbolAddress(&p, g_hid);  hid  = (float*)p;
    cudaGetSymbolAddress(&p, g_col);  col  = (float*)p;
    cudaGetSymbolAddress(&p, g_wT);   wT   = (float*)p;
    cudaGetSymbolAddress(&p, g_conv); conv = (float*)p;

    // x -> xbuf
    copy4_kernel<<<(NTOK * DD / 4 + 255) / 256, 256>>>((const float4*)x_in, (float4*)xbuf, NTOK * DD / 4);

    for (int i = 0; i < NDEPTH; i++) {
        // LN1
        ln_kernel<<<NTOK, 256>>>(xbuf, ln1_g + i * DD, ln1_b + i * DD, t0, DD);
        // QKV: [32768,256] @ [256,768] + bias
        {
            dim3 g(768 / 64, NTOK / 64);
            gemm64<EPI_BIAS><<<g, 256>>>(t0, qkv_w + (size_t)i * DD * 768, qkv_b + i * 768,
                                         nullptr, qkv, NTOK, 768, DD);
        }
        // neighborhood attention (K=7 window)
        nat_attn_kernel<<<NTOK * HH / 8, 256>>>(qkv, attn);
        // proj + bias + residual -> xbuf
        {
            dim3 g(DD / 64, NTOK / 64);
            gemm64<EPI_BIAS_RES><<<g, 256>>>(attn, proj_w + (size_t)i * DD * DD, proj_b + i * DD,
                                             xbuf, xbuf, NTOK, DD, DD);
        }
        // LN2
        ln_kernel<<<NTOK, 256>>>(xbuf, ln2_g + i * DD, ln2_b + i * DD, t0, DD);
        // fc1 + bias + exact GELU
        {
            dim3 g(1024 / 64, NTOK / 64);
            gemm64<EPI_BIAS_GELU><<<g, 256>>>(t0, fc1_w + (size_t)i * DD * 1024, fc1_b + i * 1024,
                                              nullptr, hid, NTOK, 1024, DD);
        }
        // fc2 + bias + residual -> xbuf
        {
            dim3 g(DD / 64, NTOK / 64);
            gemm64<EPI_BIAS_RES><<<g, 256>>>(hid, fc2_w + (size_t)i * 1024 * DD, fc2_b + i * DD,
                                             xbuf, xbuf, NTOK, DD, 1024);
        }
    }

    // conv1d (stride 2, pad 1, kw 3) as im2col + GEMM
    wtrans_kernel<<<(KCONV * OCH + 255) / 256, 256>>>(conv_w, wT);
    im2col_kernel<<<(BB * LOUT * KCONV + 255) / 256, 256>>>(xbuf, col);
    {
        dim3 g(OCH / 64, (BB * LOUT) / 64);
        gemm64<EPI_NONE><<<g, 256>>>(col, wT, nullptr, nullptr, conv, BB * LOUT, OCH, KCONV);
    }
    // final LayerNorm over 512 channels -> y
    ln_kernel<<<BB * LOUT, 256>>>(conv, dn_g, dn_b, y_out, OCH);
}

// round 3
// speedup vs baseline: 2.1485x; 2.1485x over previous
#include <cuda_runtime.h>
#include <cuda_bf16.h>
#include <cstdint>
#include <math.h>

#define BB 16
#define LL 2048
#define DD 256
#define HH 8
#define HDIM 32
#define KWIN 7
#define NDEPTH 2
#define LOUT 1024
#define OCH 512
#define KCONV 768
#define NTOK (BB*LL)
#define Y_ELEMS (BB*LOUT*OCH)

// ================= scratch =================
__device__ __nv_bfloat16 g_t0h[(size_t)NTOK*DD], g_t0l[(size_t)NTOK*DD];
__device__ float         g_qkv[(size_t)NTOK*3*DD];
__device__ __nv_bfloat16 g_ath[(size_t)NTOK*DD], g_atl[(size_t)NTOK*DD];
__device__ __nv_bfloat16 g_hih[(size_t)NTOK*4*DD], g_hil[(size_t)NTOK*4*DD];
__device__ __nv_bfloat16 g_colh[(size_t)BB*LOUT*KCONV], g_coll[(size_t)BB*LOUT*KCONV];
__device__ float         g_conv[(size_t)BB*LOUT*OCH];
// transposed + split weights  [N][K]
__device__ __nv_bfloat16 g_wqh[(size_t)NDEPTH*768*DD],  g_wql[(size_t)NDEPTH*768*DD];
__device__ __nv_bfloat16 g_wph[(size_t)NDEPTH*DD*DD],   g_wpl[(size_t)NDEPTH*DD*DD];
__device__ __nv_bfloat16 g_w1h[(size_t)NDEPTH*1024*DD], g_w1l[(size_t)NDEPTH*1024*DD];
__device__ __nv_bfloat16 g_w2h[(size_t)NDEPTH*DD*1024], g_w2l[(size_t)NDEPTH*DD*1024];
__device__ __nv_bfloat16 g_cwh[(size_t)OCH*KCONV],      g_cwl[(size_t)OCH*KCONV];

// ================= helpers =================
__device__ __forceinline__ uint32_t smem_u32(const void* p) {
    uint32_t a;
    asm("{ .reg .u64 t; cvta.to.shared.u64 t, %1; cvt.u32.u64 %0, t; }" : "=r"(a) : "l"(p));
    return a;
}
__device__ __forceinline__ void cp16(uint32_t s, const void* g) {
    asm volatile("cp.async.cg.shared.global [%0], [%1], 16;" :: "r"(s), "l"(g));
}
#define CP_COMMIT() asm volatile("cp.async.commit_group;" ::: "memory")
#define CP_WAIT(n)  asm volatile("cp.async.wait_group %0;" :: "n"(n) : "memory")

__device__ __forceinline__ void ldsm4(uint32_t* r, uint32_t addr) {
    asm volatile("ldmatrix.sync.aligned.m8n8.x4.shared.b16 {%0,%1,%2,%3}, [%4];"
        : "=r"(r[0]), "=r"(r[1]), "=r"(r[2]), "=r"(r[3]) : "r"(addr));
}
__device__ __forceinline__ void mma16816(float* c, const uint32_t* a, uint32_t b0, uint32_t b1) {
    asm volatile(
        "mma.sync.aligned.m16n8k16.row.col.f32.bf16.bf16.f32 "
        "{%0,%1,%2,%3}, {%4,%5,%6,%7}, {%8,%9}, {%0,%1,%2,%3};"
        : "+f"(c[0]), "+f"(c[1]), "+f"(c[2]), "+f"(c[3])
        : "r"(a[0]), "r"(a[1]), "r"(a[2]), "r"(a[3]), "r"(b0), "r"(b1));
}
__device__ __forceinline__ void split2(float v, __nv_bfloat16& h, __nv_bfloat16& l) {
    h = __float2bfloat16(v);
    l = __float2bfloat16(v - __bfloat162float(h));
}

__device__ __forceinline__ float blockReduceSum(float v) {
    __shared__ float s[8];
    int lane = threadIdx.x & 31, w = threadIdx.x >> 5;
    #pragma unroll
    for (int o = 16; o; o >>= 1) v += __shfl_xor_sync(0xffffffffu, v, o);
    if (lane == 0) s[w] = v;
    __syncthreads();
    if (w == 0) {
        v = (lane < 8) ? s[lane] : 0.0f;
        #pragma unroll
        for (int o = 4; o; o >>= 1) v += __shfl_xor_sync(0xffffffffu, v, o);
        if (lane == 0) s[0] = v;
    }
    __syncthreads();
    float r = s[0];
    __syncthreads();
    return r;
}

// ================= elementwise kernels =================
__global__ void copy4_kernel(const float4* __restrict__ src, float4* __restrict__ dst, int n4) {
    int i = blockIdx.x * blockDim.x + threadIdx.x;
    if (i < n4) dst[i] = src[i];
}

__global__ void ln_split(const float* __restrict__ x, const float* __restrict__ g,
                         const float* __restrict__ bta,
                         __nv_bfloat16* __restrict__ oh, __nv_bfloat16* __restrict__ ol) {
    int row = blockIdx.x;
    const float* xr = x + (size_t)row * DD;
    float e = xr[threadIdx.x];
    float m = blockReduceSum(e) * (1.0f / DD);
    float d = e - m;
    float var = blockReduceSum(d * d) * (1.0f / DD);
    float r = rsqrtf(var + 1e-5f);
    float v = d * r * g[threadIdx.x] + bta[threadIdx.x];
    __nv_bfloat16 h, l;
    split2(v, h, l);
    oh[(size_t)row * DD + threadIdx.x] = h;
    ol[(size_t)row * DD + threadIdx.x] = l;
}

__global__ void ln_plain(const float* __restrict__ x, const float* __restrict__ g,
                         const float* __restrict__ bta, float* __restrict__ out) {
    int row = blockIdx.x;
    const float* xr = x + (size_t)row * OCH;
    float e0 = xr[threadIdx.x], e1 = xr[threadIdx.x + 256];
    float m = blockReduceSum(e0 + e1) * (1.0f / OCH);
    float d0 = e0 - m, d1 = e1 - m;
    float var = blockReduceSum(d0 * d0 + d1 * d1) * (1.0f / OCH);
    float r = rsqrtf(var + 1e-5f);
    float* orow = out + (size_t)row * OCH;
    orow[threadIdx.x]       = d0 * r * g[threadIdx.x] + bta[threadIdx.x];
    orow[threadIdx.x + 256] = d1 * r * g[threadIdx.x + 256] + bta[threadIdx.x + 256];
}

__global__ void nat_attn_kernel(const float* __restrict__ qkv,
                                __nv_bfloat16* __restrict__ oh, __nv_bfloat16* __restrict__ ol) {
    int warp = blockIdx.x * (blockDim.x >> 5) + (threadIdx.x >> 5);
    int lane = threadIdx.x & 31;
    int h = warp & (HH - 1);
    int token = warp >> 3;
    int l = token & (LL - 1);
    int b = token >> 11;
    const float SCALE = 0.17677669529663687f;
    float q = qkv[(size_t)token * 768 + h * HDIM + lane] * SCALE;
    int start = l - (KWIN / 2);
    if (start < 0) start = 0;
    if (start > LL - KWIN) start = LL - KWIN;
    float s[KWIN], v[KWIN];
    size_t basebl = (size_t)(b * LL) * 768;
    #pragma unroll
    for (int j = 0; j < KWIN; j++) {
        size_t off = basebl + (size_t)(start + j) * 768 + h * HDIM + lane;
        float kk = qkv[off + 256];
        v[j]     = qkv[off + 512];
        float p = q * kk;
        #pragma unroll
        for (int o = 16; o; o >>= 1) p += __shfl_xor_sync(0xffffffffu, p, o);
        s[j] = p;
    }
    float mx = s[0];
    #pragma unroll
    for (int j = 1; j < KWIN; j++) mx = fmaxf(mx, s[j]);
    float sum = 0.f;
    #pragma unroll
    for (int j = 0; j < KWIN; j++) { s[j] = __expf(s[j] - mx); sum += s[j]; }
    float inv = 1.0f / sum;
    float o = 0.f;
    #pragma unroll
    for (int j = 0; j < KWIN; j++) o += s[j] * v[j];
    __nv_bfloat16 hh, llo;
    split2(o * inv, hh, llo);
    oh[(size_t)token * DD + h * HDIM + lane] = hh;
    ol[(size_t)token * DD + h * HDIM + lane] = llo;
}

__global__ void wsplit_kernel(const float* __restrict__ w,
                              __nv_bfloat16* __restrict__ th, __nv_bfloat16* __restrict__ tl,
                              int K, int N) {
    int i = blockIdx.x * blockDim.x + threadIdx.x;
    if (i >= N * K) return;
    int n = i / K, kk = i % K;
    __nv_bfloat16 h, l;
    split2(w[(size_t)kk * N + n], h, l);
    th[i] = h; tl[i] = l;
}

__global__ void fsplit_kernel(const float* __restrict__ w,
                              __nv_bfloat16* __restrict__ th, __nv_bfloat16* __restrict__ tl, int n) {
    int i = blockIdx.x * blockDim.x + threadIdx.x;
    if (i >= n) return;
    __nv_bfloat16 h, l;
    split2(w[i], h, l);
    th[i] = h; tl[i] = l;
}

__global__ void im2col_split(const float* __restrict__ x,
                             __nv_bfloat16* __restrict__ ch, __nv_bfloat16* __restrict__ cl) {
    size_t i = (size_t)blockIdx.x * blockDim.x + threadIdx.x;
    if (i >= (size_t)BB * LOUT * KCONV) return;
    int kk = (int)(i % KCONV);
    size_t m = i / KCONV;
    int lo = (int)(m % LOUT);
    int b  = (int)(m / LOUT);
    int ic = kk / 3, kh = kk % 3;
    int t = 2 * lo - 1 + kh;
    float val = 0.f;
    if (t >= 0 && t < LL) val = x[((size_t)(b * LL + t)) * DD + ic];
    __nv_bfloat16 h, l;
    split2(val, h, l);
    ch[i] = h; cl[i] = l;
}

// ================= HMMA split-bf16 GEMM =================
// C[M,N] = (Ah+Al)[M,K] @ (Bh+Bl)[N,K]^T, 3 bf16 mma passes, fp32 accum.
// CTA tile 128x128, BK=32, 8 warps (4M x 2N), cp.async double buffered.
#define EPI_NONE       0
#define EPI_BIAS       1
#define EPI_GELU_SPLIT 2
#define EPI_BIAS_RES   3

#define ROWB 80                // padded row: 32 bf16 + 8 pad = 80 bytes
#define MATB (128*ROWB)        // 10240 bytes per matrix buffer
#define STAGEB (4*MATB)        // Ah, Al, Bh, Bl
#define SMEM_SZ (2*STAGEB)     // 81920

template <int EPI>
__global__ void __launch_bounds__(256) gemm_tc(
    const __nv_bfloat16* __restrict__ Ah, const __nv_bfloat16* __restrict__ Al,
    const __nv_bfloat16* __restrict__ Bh, const __nv_bfloat16* __restrict__ Bl,
    const float* __restrict__ bias, const float* __restrict__ res,
    float* __restrict__ C, __nv_bfloat16* __restrict__ Oh, __nv_bfloat16* __restrict__ Ol,
    int M, int N, int K)
{
    extern __shared__ char smem[];
    uint32_t sb = smem_u32(smem);
    int tid = threadIdx.x;
    int warp = tid >> 5, lane = tid & 31;
    int warp_m = warp >> 1, warp_n = warp & 1;
    int m0 = blockIdx.y << 7, n0 = blockIdx.x << 7;

    float acc[2][8][4];
    #pragma unroll
    for (int i = 0; i < 2; i++)
        #pragma unroll
        for (int j = 0; j < 8; j++)
            #pragma unroll
            for (int k = 0; k < 4; k++) acc[i][j][k] = 0.f;

    // cp.async mapping: chunk c -> row = c>>2, kc = (c&3)*8 (bf16)
    int r0c = tid >> 2, kc0 = (tid & 3) * 8;
    int r1c = r0c + 64;

    // ldmatrix lane geometry
    int a_row = warp_m * 32 + (lane & 7) + ((lane >> 3) & 1) * 8;
    int a_k   = (lane >> 4) * 8;
    int b_n   = warp_n * 64 + (lane & 7) + (lane >> 4) * 8;
    int b_k   = ((lane >> 3) & 1) * 8;

    int nk = K >> 5;
    #define LOAD_STAGE(st, k0) do { \
        uint32_t base_ = sb + (st) * STAGEB; \
        uint32_t s0_ = base_ + r0c * ROWB + kc0 * 2; \
        uint32_t s1_ = base_ + r1c * ROWB + kc0 * 2; \
        size_t gA0_ = (size_t)(m0 + r0c) * K + (k0) + kc0; \
        size_t gA1_ = (size_t)(m0 + r1c) * K + (k0) + kc0; \
        size_t gB0_ = (size_t)(n0 + r0c) * K + (k0) + kc0; \
        size_t gB1_ = (size_t)(n0 + r1c) * K + (k0) + kc0; \
        cp16(s0_,            Ah + gA0_); cp16(s1_,            Ah + gA1_); \
        cp16(s0_ + MATB,     Al + gA0_); cp16(s1_ + MATB,     Al + gA1_); \
        cp16(s0_ + 2*MATB,   Bh + gB0_); cp16(s1_ + 2*MATB,   Bh + gB1_); \
        cp16(s0_ + 3*MATB,   Bl + gB0_); cp16(s1_ + 3*MATB,   Bl + gB1_); \
        CP_COMMIT(); \
    } while (0)

    LOAD_STAGE(0, 0);

    for (int kt = 0; kt < nk; kt++) {
        if (kt + 1 < nk) { LOAD_STAGE((kt + 1) & 1, (kt + 1) * 32); CP_WAIT(1); }
        else             { CP_WAIT(0); }
        __syncthreads();

        uint32_t base = sb + (kt & 1) * STAGEB;
        #pragma unroll
        for (int ks = 0; ks < 2; ks++) {
            int k = ks * 16;
            uint32_t ah[2][4], al[2][4];
            #pragma unroll
            for (int mt = 0; mt < 2; mt++) {
                uint32_t eo = base + (uint32_t)(a_row + mt * 16) * ROWB + (uint32_t)(k + a_k) * 2;
                ldsm4(ah[mt], eo);
                ldsm4(al[mt], eo + MATB);
            }
            #pragma unroll
            for (int p = 0; p < 4; p++) {
                uint32_t eo = base + 2 * MATB + (uint32_t)(b_n + p * 16) * ROWB + (uint32_t)(k + b_k) * 2;
                uint32_t bh4[4], bl4[4];
                ldsm4(bh4, eo);
                ldsm4(bl4, eo + MATB);
                #pragma unroll
                for (int mt = 0; mt < 2; mt++) {
                    mma16816(acc[mt][2 * p],     ah[mt], bh4[0], bh4[1]);
                    mma16816(acc[mt][2 * p],     ah[mt], bl4[0], bl4[1]);
                    mma16816(acc[mt][2 * p],     al[mt], bh4[0], bh4[1]);
                    mma16816(acc[mt][2 * p + 1], ah[mt], bh4[2], bh4[3]);
                    mma16816(acc[mt][2 * p + 1], ah[mt], bl4[2], bl4[3]);
                    mma16816(acc[mt][2 * p + 1], al[mt], bh4[2], bh4[3]);
                }
            }
        }
        __syncthreads();
    }

    // epilogue
    int group = lane >> 2, tg = lane & 3;
    #pragma unroll
    for (int mt = 0; mt < 2; mt++) {
        #pragma unroll
        for (int half = 0; half < 2; half++) {
            int m = m0 + warp_m * 32 + mt * 16 + group + half * 8;
            #pragma unroll
            for (int nt = 0; nt < 8; nt++) {
                int n = n0 + warp_n * 64 + nt * 8 + tg * 2;
                float v0 = acc[mt][nt][half * 2 + 0];
                float v1 = acc[mt][nt][half * 2 + 1];
                if (EPI >= 1) { v0 += bias[n]; v1 += bias[n + 1]; }
                if (EPI == EPI_GELU_SPLIT) {
                    v0 = 0.5f * v0 * (1.0f + erff(v0 * 0.70710678118654752f));
                    v1 = 0.5f * v1 * (1.0f + erff(v1 * 0.70710678118654752f));
                    __nv_bfloat16 h0, l0, h1, l1;
                    split2(v0, h0, l0); split2(v1, h1, l1);
                    *(__nv_bfloat162*)&Oh[(size_t)m * N + n] = __nv_bfloat162(h0, h1);
                    *(__nv_bfloat162*)&Ol[(size_t)m * N + n] = __nv_bfloat162(l0, l1);
                } else {
                    if (EPI == EPI_BIAS_RES) {
                        float2 rr = *(const float2*)&res[(size_t)m * N + n];
                        v0 += rr.x; v1 += rr.y;
                    }
                    *(float2*)&C[(size_t)m * N + n] = make_float2(v0, v1);
                }
            }
        }
    }
}

// ================= launch =================
extern "C" void kernel_launch(void* const* d_in, const int* in_sizes, int n_in,
                              void* d_out, int out_size)
{
    const float* x_in   = (const float*)d_in[0];
    const float* ln1_g  = (const float*)d_in[1];
    const float* ln1_b  = (const float*)d_in[2];
    const float* qkv_w  = (const float*)d_in[3];
    const float* qkv_b  = (const float*)d_in[4];
    const float* proj_w = (const float*)d_in[5];
    const float* proj_b = (const float*)d_in[6];
    const float* ln2_g  = (const float*)d_in[7];
    const float* ln2_b  = (const float*)d_in[8];
    const float* fc1_w  = (const float*)d_in[9];
    const float* fc1_b  = (const float*)d_in[10];
    const float* fc2_w  = (const float*)d_in[11];
    const float* fc2_b  = (const float*)d_in[12];
    const float* conv_w = (const float*)d_in[13];
    const float* dn_g   = (const float*)d_in[14];
    const float* dn_b   = (const float*)d_in[15];

    float* y_out = (float*)d_out;
    float* xbuf  = y_out + Y_ELEMS;

    void* p;
    #define GET(sym, var) cudaGetSymbolAddress(&p, sym); auto* var = (decltype(&sym[0]))p;
    GET(g_t0h, t0h) GET(g_t0l, t0l) GET(g_qkv, qkv)
    GET(g_ath, ath) GET(g_atl, atl)
    GET(g_hih, hih) GET(g_hil, hil)
    GET(g_colh, colh) GET(g_coll, coll) GET(g_conv, conv)
    GET(g_wqh, wqh) GET(g_wql, wql) GET(g_wph, wph) GET(g_wpl, wpl)
    GET(g_w1h, w1h) GET(g_w1l, w1l) GET(g_w2h, w2h) GET(g_w2l, w2l)
    GET(g_cwh, cwh) GET(g_cwl, cwl)
    #undef GET

    cudaFuncSetAttribute(gemm_tc<EPI_NONE>,       cudaFuncAttributeMaxDynamicSharedMemorySize, SMEM_SZ);
    cudaFuncSetAttribute(gemm_tc<EPI_BIAS>,       cudaFuncAttributeMaxDynamicSharedMemorySize, SMEM_SZ);
    cudaFuncSetAttribute(gemm_tc<EPI_GELU_SPLIT>, cudaFuncAttributeMaxDynamicSharedMemorySize, SMEM_SZ);
    cudaFuncSetAttribute(gemm_tc<EPI_BIAS_RES>,   cudaFuncAttributeMaxDynamicSharedMemorySize, SMEM_SZ);

    // weight prep (transpose + bf16 split)
    for (int i = 0; i < NDEPTH; i++) {
        wsplit_kernel<<<(768 * DD + 255) / 256, 256>>>(qkv_w + (size_t)i * DD * 768,
            wqh + (size_t)i * 768 * DD, wql + (size_t)i * 768 * DD, DD, 768);
        wsplit_kernel<<<(DD * DD + 255) / 256, 256>>>(proj_w + (size_t)i * DD * DD,
            wph + (size_t)i * DD * DD, wpl + (size_t)i * DD * DD, DD, DD);
        wsplit_kernel<<<(1024 * DD + 255) / 256, 256>>>(fc1_w + (size_t)i * DD * 1024,
            w1h + (size_t)i * 1024 * DD, w1l + (size_t)i * 1024 * DD, DD, 1024);
        wsplit_kernel<<<(DD * 1024 + 255) / 256, 256>>>(fc2_w + (size_t)i * 1024 * DD,
            w2h + (size_t)i * DD * 1024, w2l + (size_t)i * DD * 1024, 1024, DD);
    }
    fsplit_kernel<<<(OCH * KCONV + 255) / 256, 256>>>(conv_w, cwh, cwl, OCH * KCONV);

    copy4_kernel<<<(NTOK * DD / 4 + 255) / 256, 256>>>((const float4*)x_in, (float4*)xbuf, NTOK * DD / 4);

    for (int i = 0; i < NDEPTH; i++) {
        ln_split<<<NTOK, 256>>>(xbuf, ln1_g + i * DD, ln1_b + i * DD, t0h, t0l);
        {   // qkv
            dim3 g(768 / 128, NTOK / 128);
            gemm_tc<EPI_BIAS><<<g, 256, SMEM_SZ>>>(t0h, t0l,
                wqh + (size_t)i * 768 * DD, wql + (size_t)i * 768 * DD,
                qkv_b + i * 768, nullptr, qkv, nullptr, nullptr, NTOK, 768, DD);
        }
        nat_attn_kernel<<<NTOK * HH / 8, 256>>>(qkv, ath, atl);
        {   // proj + residual
            dim3 g(DD / 128, NTOK / 128);
            gemm_tc<EPI_BIAS_RES><<<g, 256, SMEM_SZ>>>(ath, atl,
                wph + (size_t)i * DD * DD, wpl + (size_t)i * DD * DD,
                proj_b + i * DD, xbuf, xbuf, nullptr, nullptr, NTOK, DD, DD);
        }
        ln_split<<<NTOK, 256>>>(xbuf, ln2_g + i * DD, ln2_b + i * DD, t0h, t0l);
        {   // fc1 + gelu -> bf16 split
            dim3 g(1024 / 128, NTOK / 128);
            gemm_tc<EPI_GELU_SPLIT><<<g, 256, SMEM_SZ>>>(t0h, t0l,
                w1h + (size_t)i * 1024 * DD, w1l + (size_t)i * 1024 * DD,
                fc1_b + i * 1024, nullptr, nullptr, hih, hil, NTOK, 1024, DD);
        }
        {   // fc2 + residual
            dim3 g(DD / 128, NTOK / 128);
            gemm_tc<EPI_BIAS_RES><<<g, 256, SMEM_SZ>>>(hih, hil,
                w2h + (size_t)i * DD * 1024, w2l + (size_t)i * DD * 1024,
                fc2_b + i * DD, xbuf, xbuf, nullptr, nullptr, NTOK, DD, 1024);
        }
    }

    // conv as im2col + GEMM
    im2col_split<<<(BB * LOUT * KCONV + 255) / 256, 256>>>(xbuf, colh, coll);
    {
        dim3 g(OCH / 128, (BB * LOUT) / 128);
        gemm_tc<EPI_NONE><<<g, 256, SMEM_SZ>>>(colh, coll, cwh, cwl,
            nullptr, nullptr, conv, nullptr, nullptr, BB * LOUT, OCH, KCONV);
    }
    ln_plain<<<BB * LOUT, 256>>>(conv, dn_g, dn_b, y_out);
}

// round 4
// speedup vs baseline: 2.6269x; 1.2227x over previous
#include <cuda_runtime.h>
#include <cuda_fp16.h>
#include <cstdint>
#include <math.h>

#define BB 16
#define LL 2048
#define DD 256
#define HH 8
#define HDIM 32
#define KWIN 7
#define NDEPTH 2
#define LOUT 1024
#define OCH 512
#define KCONV 768
#define NTOK (BB*LL)
#define Y_ELEMS (BB*LOUT*OCH)

// ================= scratch =================
__device__ __half g_t0h[(size_t)NTOK*DD], g_t0l[(size_t)NTOK*DD];
__device__ float  g_qkv[(size_t)NTOK*3*DD];
__device__ __half g_ath[(size_t)NTOK*DD], g_atl[(size_t)NTOK*DD];
__device__ __half g_hih[(size_t)NTOK*4*DD], g_hil[(size_t)NTOK*4*DD];
__device__ __half g_colh[(size_t)BB*LOUT*KCONV], g_coll[(size_t)BB*LOUT*KCONV];
__device__ float  g_conv[(size_t)BB*LOUT*OCH];
// transposed fp16 weights [N][K]
__device__ __half g_wq[(size_t)NDEPTH*768*DD];
__device__ __half g_wp[(size_t)NDEPTH*DD*DD];
__device__ __half g_w1[(size_t)NDEPTH*1024*DD];
__device__ __half g_w2[(size_t)NDEPTH*DD*1024];
__device__ __half g_cw[(size_t)OCH*KCONV];

// ================= helpers =================
__device__ __forceinline__ uint32_t smem_u32(const void* p) {
    uint32_t a;
    asm("{ .reg .u64 t; cvta.to.shared.u64 t, %1; cvt.u32.u64 %0, t; }" : "=r"(a) : "l"(p));
    return a;
}
__device__ __forceinline__ void cp16(uint32_t s, const void* g) {
    asm volatile("cp.async.cg.shared.global [%0], [%1], 16;" :: "r"(s), "l"(g));
}
#define CP_COMMIT() asm volatile("cp.async.commit_group;" ::: "memory")
#define CP_WAIT(n)  asm volatile("cp.async.wait_group %0;" :: "n"(n) : "memory")

__device__ __forceinline__ void ldsm4(uint32_t* r, uint32_t addr) {
    asm volatile("ldmatrix.sync.aligned.m8n8.x4.shared.b16 {%0,%1,%2,%3}, [%4];"
        : "=r"(r[0]), "=r"(r[1]), "=r"(r[2]), "=r"(r[3]) : "r"(addr));
}
__device__ __forceinline__ void mma16816(float* c, const uint32_t* a, uint32_t b0, uint32_t b1) {
    asm volatile(
        "mma.sync.aligned.m16n8k16.row.col.f32.f16.f16.f32 "
        "{%0,%1,%2,%3}, {%4,%5,%6,%7}, {%8,%9}, {%0,%1,%2,%3};"
        : "+f"(c[0]), "+f"(c[1]), "+f"(c[2]), "+f"(c[3])
        : "r"(a[0]), "r"(a[1]), "r"(a[2]), "r"(a[3]), "r"(b0), "r"(b1));
}
__device__ __forceinline__ void split2h(float v, __half& h, __half& l) {
    h = __float2half_rn(v);
    l = __float2half_rn(v - __half2float(h));
}

__device__ __forceinline__ float blockReduceSum(float v) {
    __shared__ float s[8];
    int lane = threadIdx.x & 31, w = threadIdx.x >> 5;
    #pragma unroll
    for (int o = 16; o; o >>= 1) v += __shfl_xor_sync(0xffffffffu, v, o);
    if (lane == 0) s[w] = v;
    __syncthreads();
    if (w == 0) {
        v = (lane < 8) ? s[lane] : 0.0f;
        #pragma unroll
        for (int o = 4; o; o >>= 1) v += __shfl_xor_sync(0xffffffffu, v, o);
        if (lane == 0) s[0] = v;
    }
    __syncthreads();
    float r = s[0];
    __syncthreads();
    return r;
}

// ================= combined weight prep =================
// all weights transposed [K][N] -> [N][K] and rounded to fp16
#define S_WQ  (768*DD)
#define S_WP  (DD*DD)
#define S_W1  (1024*DD)
#define S_W2  (DD*1024)
#define LAYER_ELEMS (S_WQ + S_WP + S_W1 + S_W2)        // 786432
#define PREP_TOTAL  (2*LAYER_ELEMS + OCH*KCONV)        // 1966080

__device__ __forceinline__ __half tr_h(const float* src, int j, int K, int N) {
    int n = j / K, kk = j % K;
    return __float2half_rn(src[(size_t)kk * N + n]);
}

__global__ void prep_kernel(const float* __restrict__ qkv_w, const float* __restrict__ proj_w,
                            const float* __restrict__ fc1_w, const float* __restrict__ fc2_w,
                            const float* __restrict__ conv_w,
                            __half* __restrict__ wq, __half* __restrict__ wp,
                            __half* __restrict__ w1, __half* __restrict__ w2,
                            __half* __restrict__ cw) {
    int i = blockIdx.x * blockDim.x + threadIdx.x;
    if (i >= PREP_TOTAL) return;
    if (i < 2 * LAYER_ELEMS) {
        int layer = i / LAYER_ELEMS;
        int j = i - layer * LAYER_ELEMS;
        if (j < S_WQ)
            wq[(size_t)layer * S_WQ + j] = tr_h(qkv_w + (size_t)layer * S_WQ, j, DD, 768);
        else if (j < S_WQ + S_WP)
            wp[(size_t)layer * S_WP + (j - S_WQ)] = tr_h(proj_w + (size_t)layer * S_WP, j - S_WQ, DD, DD);
        else if (j < S_WQ + S_WP + S_W1)
            w1[(size_t)layer * S_W1 + (j - S_WQ - S_WP)] = tr_h(fc1_w + (size_t)layer * S_W1, j - S_WQ - S_WP, DD, 1024);
        else
            w2[(size_t)layer * S_W2 + (j - S_WQ - S_WP - S_W1)] = tr_h(fc2_w + (size_t)layer * S_W2, j - S_WQ - S_WP - S_W1, 1024, DD);
    } else {
        int j = i - 2 * LAYER_ELEMS;        // conv already [OCH][KCONV] = [N][K]
        cw[j] = __float2half_rn(conv_w[j]);
    }
}

// ================= elementwise kernels =================
__global__ void ln_split(const float* __restrict__ x, const float* __restrict__ g,
                         const float* __restrict__ bta,
                         __half* __restrict__ oh, __half* __restrict__ ol) {
    int row = blockIdx.x;
    const float* xr = x + (size_t)row * DD;
    float e = xr[threadIdx.x];
    float m = blockReduceSum(e) * (1.0f / DD);
    float d = e - m;
    float var = blockReduceSum(d * d) * (1.0f / DD);
    float r = rsqrtf(var + 1e-5f);
    float v = d * r * g[threadIdx.x] + bta[threadIdx.x];
    __half h, l;
    split2h(v, h, l);
    oh[(size_t)row * DD + threadIdx.x] = h;
    ol[(size_t)row * DD + threadIdx.x] = l;
}

__global__ void ln_plain(const float* __restrict__ x, const float* __restrict__ g,
                         const float* __restrict__ bta, float* __restrict__ out) {
    int row = blockIdx.x;
    const float* xr = x + (size_t)row * OCH;
    float e0 = xr[threadIdx.x], e1 = xr[threadIdx.x + 256];
    float m = blockReduceSum(e0 + e1) * (1.0f / OCH);
    float d0 = e0 - m, d1 = e1 - m;
    float var = blockReduceSum(d0 * d0 + d1 * d1) * (1.0f / OCH);
    float r = rsqrtf(var + 1e-5f);
    float* orow = out + (size_t)row * OCH;
    orow[threadIdx.x]       = d0 * r * g[threadIdx.x] + bta[threadIdx.x];
    orow[threadIdx.x + 256] = d1 * r * g[threadIdx.x + 256] + bta[threadIdx.x + 256];
}

__global__ void nat_attn_kernel(const float* __restrict__ qkv,
                                __half* __restrict__ oh, __half* __restrict__ ol) {
    int warp = blockIdx.x * (blockDim.x >> 5) + (threadIdx.x >> 5);
    int lane = threadIdx.x & 31;
    int h = warp & (HH - 1);
    int token = warp >> 3;
    int l = token & (LL - 1);
    int b = token >> 11;
    const float SCALE = 0.17677669529663687f;
    float q = qkv[(size_t)token * 768 + h * HDIM + lane] * SCALE;
    int start = l - (KWIN / 2);
    if (start < 0) start = 0;
    if (start > LL - KWIN) start = LL - KWIN;
    float s[KWIN], v[KWIN];
    size_t basebl = (size_t)(b * LL) * 768;
    #pragma unroll
    for (int j = 0; j < KWIN; j++) {
        size_t off = basebl + (size_t)(start + j) * 768 + h * HDIM + lane;
        float kk = qkv[off + 256];
        v[j]     = qkv[off + 512];
        float p = q * kk;
        #pragma unroll
        for (int o = 16; o; o >>= 1) p += __shfl_xor_sync(0xffffffffu, p, o);
        s[j] = p;
    }
    float mx = s[0];
    #pragma unroll
    for (int j = 1; j < KWIN; j++) mx = fmaxf(mx, s[j]);
    float sum = 0.f;
    #pragma unroll
    for (int j = 0; j < KWIN; j++) { s[j] = __expf(s[j] - mx); sum += s[j]; }
    float inv = 1.0f / sum;
    float o = 0.f;
    #pragma unroll
    for (int j = 0; j < KWIN; j++) o += s[j] * v[j];
    __half hh, llo;
    split2h(o * inv, hh, llo);
    oh[(size_t)token * DD + h * HDIM + lane] = hh;
    ol[(size_t)token * DD + h * HDIM + lane] = llo;
}

__global__ void im2col_split(const float* __restrict__ x,
                             __half* __restrict__ ch, __half* __restrict__ cl) {
    size_t i = (size_t)blockIdx.x * blockDim.x + threadIdx.x;
    if (i >= (size_t)BB * LOUT * KCONV) return;
    int kk = (int)(i % KCONV);
    size_t m = i / KCONV;
    int lo = (int)(m % LOUT);
    int b  = (int)(m / LOUT);
    int ic = kk / 3, kh = kk % 3;
    int t = 2 * lo - 1 + kh;
    float val = 0.f;
    if (t >= 0 && t < LL) val = x[((size_t)(b * LL + t)) * DD + ic];
    __half h, l;
    split2h(val, h, l);
    ch[i] = h; cl[i] = l;
}

// ================= HMMA split-fp16 GEMM (2 passes) =================
// C[M,N] = (Ah+Al)[M,K] @ B[N,K]^T, fp32 accum. A split exact; B single fp16.
// CTA tile 128x128, BK=32, 8 warps (4M x 2N), cp.async double buffered.
#define EPI_NONE       0
#define EPI_BIAS       1
#define EPI_GELU_SPLIT 2
#define EPI_BIAS_RES   3

#define ROWB 80                // padded row: 32 fp16 + 8 pad = 80 bytes
#define MATB (128*ROWB)        // 10240 bytes per matrix buffer
#define STAGEB (3*MATB)        // Ah, Al, B
#define SMEM_SZ (2*STAGEB)     // 61440

template <int EPI>
__global__ void __launch_bounds__(256) gemm_tc(
    const __half* __restrict__ Ah, const __half* __restrict__ Al,
    const __half* __restrict__ Bm,
    const float* __restrict__ bias, const float* __restrict__ res,
    float* __restrict__ C, __half* __restrict__ Oh, __half* __restrict__ Ol,
    int M, int N, int K)
{
    extern __shared__ char smem[];
    uint32_t sb = smem_u32(smem);
    int tid = threadIdx.x;
    int warp = tid >> 5, lane = tid & 31;
    int warp_m = warp >> 1, warp_n = warp & 1;
    int m0 = blockIdx.y << 7, n0 = blockIdx.x << 7;

    float acc[2][8][4];
    #pragma unroll
    for (int i = 0; i < 2; i++)
        #pragma unroll
        for (int j = 0; j < 8; j++)
            #pragma unroll
            for (int k = 0; k < 4; k++) acc[i][j][k] = 0.f;

    int r0c = tid >> 2, kc0 = (tid & 3) * 8;
    int r1c = r0c + 64;

    int a_row = warp_m * 32 + (lane & 7) + ((lane >> 3) & 1) * 8;
    int a_k   = (lane >> 4) * 8;
    int b_n   = warp_n * 64 + (lane & 7) + (lane >> 4) * 8;
    int b_k   = ((lane >> 3) & 1) * 8;

    int nk = K >> 5;
    #define LOAD_STAGE(st, k0) do { \
        uint32_t base_ = sb + (st) * STAGEB; \
        uint32_t s0_ = base_ + r0c * ROWB + kc0 * 2; \
        uint32_t s1_ = base_ + r1c * ROWB + kc0 * 2; \
        size_t gA0_ = (size_t)(m0 + r0c) * K + (k0) + kc0; \
        size_t gA1_ = (size_t)(m0 + r1c) * K + (k0) + kc0; \
        size_t gB0_ = (size_t)(n0 + r0c) * K + (k0) + kc0; \
        size_t gB1_ = (size_t)(n0 + r1c) * K + (k0) + kc0; \
        cp16(s0_,          Ah + gA0_); cp16(s1_,          Ah + gA1_); \
        cp16(s0_ + MATB,   Al + gA0_); cp16(s1_ + MATB,   Al + gA1_); \
        cp16(s0_ + 2*MATB, Bm + gB0_); cp16(s1_ + 2*MATB, Bm + gB1_); \
        CP_COMMIT(); \
    } while (0)

    LOAD_STAGE(0, 0);

    for (int kt = 0; kt < nk; kt++) {
        if (kt + 1 < nk) { LOAD_STAGE((kt + 1) & 1, (kt + 1) * 32); CP_WAIT(1); }
        else             { CP_WAIT(0); }
        __syncthreads();

        uint32_t base = sb + (kt & 1) * STAGEB;
        #pragma unroll
        for (int ks = 0; ks < 2; ks++) {
            int k = ks * 16;
            uint32_t ah[2][4], al[2][4];
            #pragma unroll
            for (int mt = 0; mt < 2; mt++) {
                uint32_t eo = base + (uint32_t)(a_row + mt * 16) * ROWB + (uint32_t)(k + a_k) * 2;
                ldsm4(ah[mt], eo);
                ldsm4(al[mt], eo + MATB);
            }
            #pragma unroll
            for (int p = 0; p < 4; p++) {
                uint32_t eo = base + 2 * MATB + (uint32_t)(b_n + p * 16) * ROWB + (uint32_t)(k + b_k) * 2;
                uint32_t b4[4];
                ldsm4(b4, eo);
                #pragma unroll
                for (int mt = 0; mt < 2; mt++) {
                    mma16816(acc[mt][2 * p],     ah[mt], b4[0], b4[1]);
                    mma16816(acc[mt][2 * p],     al[mt], b4[0], b4[1]);
                    mma16816(acc[mt][2 * p + 1], ah[mt], b4[2], b4[3]);
                    mma16816(acc[mt][2 * p + 1], al[mt], b4[2], b4[3]);
                }
            }
        }
        __syncthreads();
    }

    // epilogue
    int group = lane >> 2, tg = lane & 3;
    #pragma unroll
    for (int mt = 0; mt < 2; mt++) {
        #pragma unroll
        for (int half = 0; half < 2; half++) {
            int m = m0 + warp_m * 32 + mt * 16 + group + half * 8;
            #pragma unroll
            for (int nt = 0; nt < 8; nt++) {
                int n = n0 + warp_n * 64 + nt * 8 + tg * 2;
                float v0 = acc[mt][nt][half * 2 + 0];
                float v1 = acc[mt][nt][half * 2 + 1];
                if (EPI >= 1) { v0 += bias[n]; v1 += bias[n + 1]; }
                if (EPI == EPI_GELU_SPLIT) {
                    v0 = 0.5f * v0 * (1.0f + erff(v0 * 0.70710678118654752f));
                    v1 = 0.5f * v1 * (1.0f + erff(v1 * 0.70710678118654752f));
                    __half h0, l0, h1, l1;
                    split2h(v0, h0, l0); split2h(v1, h1, l1);
                    *(__half2*)&Oh[(size_t)m * N + n] = __halves2half2(h0, h1);
                    *(__half2*)&Ol[(size_t)m * N + n] = __halves2half2(l0, l1);
                } else {
                    if (EPI == EPI_BIAS_RES) {
                        float2 rr = *(const float2*)&res[(size_t)m * N + n];
                        v0 += rr.x; v1 += rr.y;
                    }
                    *(float2*)&C[(size_t)m * N + n] = make_float2(v0, v1);
                }
            }
        }
    }
}

// ================= launch =================
extern "C" void kernel_launch(void* const* d_in, const int* in_sizes, int n_in,
                              void* d_out, int out_size)
{
    const float* x_in   = (const float*)d_in[0];
    const float* ln1_g  = (const float*)d_in[1];
    const float* ln1_b  = (const float*)d_in[2];
    const float* qkv_w  = (const float*)d_in[3];
    const float* qkv_b  = (const float*)d_in[4];
    const float* proj_w = (const float*)d_in[5];
    const float* proj_b = (const float*)d_in[6];
    const float* ln2_g  = (const float*)d_in[7];
    const float* ln2_b  = (const float*)d_in[8];
    const float* fc1_w  = (const float*)d_in[9];
    const float* fc1_b  = (const float*)d_in[10];
    const float* fc2_w  = (const float*)d_in[11];
    const float* fc2_b  = (const float*)d_in[12];
    const float* conv_w = (const float*)d_in[13];
    const float* dn_g   = (const float*)d_in[14];
    const float* dn_b   = (const float*)d_in[15];

    float* y_out = (float*)d_out;
    float* xbuf  = y_out + Y_ELEMS;

    void* p;
    #define GET(sym, var) cudaGetSymbolAddress(&p, sym); auto* var = (decltype(&sym[0]))p;
    GET(g_t0h, t0h) GET(g_t0l, t0l) GET(g_qkv, qkv)
    GET(g_ath, ath) GET(g_atl, atl)
    GET(g_hih, hih) GET(g_hil, hil)
    GET(g_colh, colh) GET(g_coll, coll) GET(g_conv, conv)
    GET(g_wq, wq) GET(g_wp, wp) GET(g_w1, w1) GET(g_w2, w2) GET(g_cw, cw)
    #undef GET

    cudaFuncSetAttribute(gemm_tc<EPI_NONE>,       cudaFuncAttributeMaxDynamicSharedMemorySize, SMEM_SZ);
    cudaFuncSetAttribute(gemm_tc<EPI_BIAS>,       cudaFuncAttributeMaxDynamicSharedMemorySize, SMEM_SZ);
    cudaFuncSetAttribute(gemm_tc<EPI_GELU_SPLIT>, cudaFuncAttributeMaxDynamicSharedMemorySize, SMEM_SZ);
    cudaFuncSetAttribute(gemm_tc<EPI_BIAS_RES>,   cudaFuncAttributeMaxDynamicSharedMemorySize, SMEM_SZ);

    // one-shot weight prep (transpose + fp16 round)
    prep_kernel<<<PREP_TOTAL / 256, 256>>>(qkv_w, proj_w, fc1_w, fc2_w, conv_w, wq, wp, w1, w2, cw);

    for (int i = 0; i < NDEPTH; i++) {
        const float* xin = (i == 0) ? x_in : xbuf;   // layer-0 reads harness input directly
        ln_split<<<NTOK, 256>>>(xin, ln1_g + i * DD, ln1_b + i * DD, t0h, t0l);
        {   // qkv
            dim3 g(768 / 128, NTOK / 128);
            gemm_tc<EPI_BIAS><<<g, 256, SMEM_SZ>>>(t0h, t0l, wq + (size_t)i * 768 * DD,
                qkv_b + i * 768, nullptr, qkv, nullptr, nullptr, NTOK, 768, DD);
        }
        nat_attn_kernel<<<NTOK * HH / 8, 256>>>(qkv, ath, atl);
        {   // proj + residual (res = x_in for layer 0, xbuf afterwards)
            dim3 g(DD / 128, NTOK / 128);
            gemm_tc<EPI_BIAS_RES><<<g, 256, SMEM_SZ>>>(ath, atl, wp + (size_t)i * DD * DD,
                proj_b + i * DD, xin, xbuf, nullptr, nullptr, NTOK, DD, DD);
        }
        ln_split<<<NTOK, 256>>>(xbuf, ln2_g + i * DD, ln2_b + i * DD, t0h, t0l);
        {   // fc1 + gelu -> fp16 split
            dim3 g(1024 / 128, NTOK / 128);
            gemm_tc<EPI_GELU_SPLIT><<<g, 256, SMEM_SZ>>>(t0h, t0l, w1 + (size_t)i * 1024 * DD,
                fc1_b + i * 1024, nullptr, nullptr, hih, hil, NTOK, 1024, DD);
        }
        {   // fc2 + residual
            dim3 g(DD / 128, NTOK / 128);
            gemm_tc<EPI_BIAS_RES><<<g, 256, SMEM_SZ>>>(hih, hil, w2 + (size_t)i * DD * 1024,
                fc2_b + i * DD, xbuf, xbuf, nullptr, nullptr, NTOK, DD, 1024);
        }
    }

    // conv as im2col + GEMM
    im2col_split<<<(BB * LOUT * KCONV + 255) / 256, 256>>>(xbuf, colh, coll);
    {
        dim3 g(OCH / 128, (BB * LOUT) / 128);
        gemm_tc<EPI_NONE><<<g, 256, SMEM_SZ>>>(colh, coll, cw,
            nullptr, nullptr, conv, nullptr, nullptr, BB * LOUT, OCH, KCONV);
    }
    ln_plain<<<BB * LOUT, 256>>>(conv, dn_g, dn_b, y_out);
}

// round 5
// speedup vs baseline: 4.1702x; 1.5875x over previous
#include <cuda_runtime.h>
#include <cuda_fp16.h>
#include <cstdint>
#include <math.h>

#define BB 16
#define LL 2048
#define DD 256
#define HH 8
#define HDIM 32
#define KWIN 7
#define NDEPTH 2
#define LOUT 1024
#define OCH 512
#define KCONV 768
#define NTOK (BB*LL)
#define Y_ELEMS (BB*LOUT*OCH)

// ================= scratch =================
__device__ __half g_t0[(size_t)NTOK*DD];
__device__ float  g_qkv[(size_t)NTOK*3*DD];
__device__ __half g_at[(size_t)NTOK*DD];
__device__ __half g_hi[(size_t)NTOK*4*DD];
__device__ __half g_col[(size_t)BB*LOUT*KCONV];
__device__ float  g_conv[(size_t)BB*LOUT*OCH];
// transposed fp16 weights [N][K]
__device__ __half g_wq[(size_t)NDEPTH*768*DD];
__device__ __half g_wp[(size_t)NDEPTH*DD*DD];
__device__ __half g_w1[(size_t)NDEPTH*1024*DD];
__device__ __half g_w2[(size_t)NDEPTH*DD*1024];
__device__ __half g_cw[(size_t)OCH*KCONV];

// ================= helpers =================
__device__ __forceinline__ uint32_t smem_u32(const void* p) {
    uint32_t a;
    asm("{ .reg .u64 t; cvta.to.shared.u64 t, %1; cvt.u32.u64 %0, t; }" : "=r"(a) : "l"(p));
    return a;
}
__device__ __forceinline__ void cp16(uint32_t s, const void* g) {
    asm volatile("cp.async.cg.shared.global [%0], [%1], 16;" :: "r"(s), "l"(g));
}
#define CP_COMMIT() asm volatile("cp.async.commit_group;" ::: "memory")
#define CP_WAIT(n)  asm volatile("cp.async.wait_group %0;" :: "n"(n) : "memory")

__device__ __forceinline__ void ldsm4(uint32_t* r, uint32_t addr) {
    asm volatile("ldmatrix.sync.aligned.m8n8.x4.shared.b16 {%0,%1,%2,%3}, [%4];"
        : "=r"(r[0]), "=r"(r[1]), "=r"(r[2]), "=r"(r[3]) : "r"(addr));
}
__device__ __forceinline__ void mma16816(float* c, const uint32_t* a, uint32_t b0, uint32_t b1) {
    asm volatile(
        "mma.sync.aligned.m16n8k16.row.col.f32.f16.f16.f32 "
        "{%0,%1,%2,%3}, {%4,%5,%6,%7}, {%8,%9}, {%0,%1,%2,%3};"
        : "+f"(c[0]), "+f"(c[1]), "+f"(c[2]), "+f"(c[3])
        : "r"(a[0]), "r"(a[1]), "r"(a[2]), "r"(a[3]), "r"(b0), "r"(b1));
}

__device__ __forceinline__ float blockReduceSum(float v) {
    __shared__ float s[8];
    int lane = threadIdx.x & 31, w = threadIdx.x >> 5;
    #pragma unroll
    for (int o = 16; o; o >>= 1) v += __shfl_xor_sync(0xffffffffu, v, o);
    if (lane == 0) s[w] = v;
    __syncthreads();
    if (w == 0) {
        v = (lane < 8) ? s[lane] : 0.0f;
        #pragma unroll
        for (int o = 4; o; o >>= 1) v += __shfl_xor_sync(0xffffffffu, v, o);
        if (lane == 0) s[0] = v;
    }
    __syncthreads();
    float r = s[0];
    __syncthreads();
    return r;
}

// ================= combined weight prep =================
#define S_WQ  (768*DD)
#define S_WP  (DD*DD)
#define S_W1  (1024*DD)
#define S_W2  (DD*1024)
#define LAYER_ELEMS (S_WQ + S_WP + S_W1 + S_W2)
#define PREP_TOTAL  (2*LAYER_ELEMS + OCH*KCONV)

__device__ __forceinline__ __half tr_h(const float* src, int j, int K, int N) {
    int n = j / K, kk = j % K;
    return __float2half_rn(src[(size_t)kk * N + n]);
}

__global__ void prep_kernel(const float* __restrict__ qkv_w, const float* __restrict__ proj_w,
                            const float* __restrict__ fc1_w, const float* __restrict__ fc2_w,
                            const float* __restrict__ conv_w,
                            __half* __restrict__ wq, __half* __restrict__ wp,
                            __half* __restrict__ w1, __half* __restrict__ w2,
                            __half* __restrict__ cw) {
    int i = blockIdx.x * blockDim.x + threadIdx.x;
    if (i >= PREP_TOTAL) return;
    if (i < 2 * LAYER_ELEMS) {
        int layer = i / LAYER_ELEMS;
        int j = i - layer * LAYER_ELEMS;
        if (j < S_WQ)
            wq[(size_t)layer * S_WQ + j] = tr_h(qkv_w + (size_t)layer * S_WQ, j, DD, 768);
        else if (j < S_WQ + S_WP)
            wp[(size_t)layer * S_WP + (j - S_WQ)] = tr_h(proj_w + (size_t)layer * S_WP, j - S_WQ, DD, DD);
        else if (j < S_WQ + S_WP + S_W1)
            w1[(size_t)layer * S_W1 + (j - S_WQ - S_WP)] = tr_h(fc1_w + (size_t)layer * S_W1, j - S_WQ - S_WP, DD, 1024);
        else
            w2[(size_t)layer * S_W2 + (j - S_WQ - S_WP - S_W1)] = tr_h(fc2_w + (size_t)layer * S_W2, j - S_WQ - S_WP - S_W1, 1024, DD);
    } else {
        int j = i - 2 * LAYER_ELEMS;
        cw[j] = __float2half_rn(conv_w[j]);
    }
}

// ================= elementwise kernels =================
__global__ void ln_h(const float* __restrict__ x, const float* __restrict__ g,
                     const float* __restrict__ bta, __half* __restrict__ o) {
    int row = blockIdx.x;
    const float* xr = x + (size_t)row * DD;
    float e = xr[threadIdx.x];
    float m = blockReduceSum(e) * (1.0f / DD);
    float d = e - m;
    float var = blockReduceSum(d * d) * (1.0f / DD);
    float r = rsqrtf(var + 1e-5f);
    float v = d * r * g[threadIdx.x] + bta[threadIdx.x];
    o[(size_t)row * DD + threadIdx.x] = __float2half_rn(v);
}

__global__ void ln_plain(const float* __restrict__ x, const float* __restrict__ g,
                         const float* __restrict__ bta, float* __restrict__ out) {
    int row = blockIdx.x;
    const float* xr = x + (size_t)row * OCH;
    float e0 = xr[threadIdx.x], e1 = xr[threadIdx.x + 256];
    float m = blockReduceSum(e0 + e1) * (1.0f / OCH);
    float d0 = e0 - m, d1 = e1 - m;
    float var = blockReduceSum(d0 * d0 + d1 * d1) * (1.0f / OCH);
    float r = rsqrtf(var + 1e-5f);
    float* orow = out + (size_t)row * OCH;
    orow[threadIdx.x]       = d0 * r * g[threadIdx.x] + bta[threadIdx.x];
    orow[threadIdx.x + 256] = d1 * r * g[threadIdx.x + 256] + bta[threadIdx.x + 256];
}

__global__ void nat_attn_kernel(const float* __restrict__ qkv, __half* __restrict__ o) {
    int warp = blockIdx.x * (blockDim.x >> 5) + (threadIdx.x >> 5);
    int lane = threadIdx.x & 31;
    int h = warp & (HH - 1);
    int token = warp >> 3;
    int l = token & (LL - 1);
    int b = token >> 11;
    const float SCALE = 0.17677669529663687f;
    float q = qkv[(size_t)token * 768 + h * HDIM + lane] * SCALE;
    int start = l - (KWIN / 2);
    if (start < 0) start = 0;
    if (start > LL - KWIN) start = LL - KWIN;
    float s[KWIN], v[KWIN];
    size_t basebl = (size_t)(b * LL) * 768;
    #pragma unroll
    for (int j = 0; j < KWIN; j++) {
        size_t off = basebl + (size_t)(start + j) * 768 + h * HDIM + lane;
        float kk = qkv[off + 256];
        v[j]     = qkv[off + 512];
        float p = q * kk;
        #pragma unroll
        for (int ofs = 16; ofs; ofs >>= 1) p += __shfl_xor_sync(0xffffffffu, p, ofs);
        s[j] = p;
    }
    float mx = s[0];
    #pragma unroll
    for (int j = 1; j < KWIN; j++) mx = fmaxf(mx, s[j]);
    float sum = 0.f;
    #pragma unroll
    for (int j = 0; j < KWIN; j++) { s[j] = __expf(s[j] - mx); sum += s[j]; }
    float inv = 1.0f / sum;
    float out = 0.f;
    #pragma unroll
    for (int j = 0; j < KWIN; j++) out += s[j] * v[j];
    o[(size_t)token * DD + h * HDIM + lane] = __float2half_rn(out * inv);
}

__global__ void im2col_h(const float* __restrict__ x, __half* __restrict__ c) {
    size_t i = (size_t)blockIdx.x * blockDim.x + threadIdx.x;
    if (i >= (size_t)BB * LOUT * KCONV) return;
    int kk = (int)(i % KCONV);
    size_t m = i / KCONV;
    int lo = (int)(m % LOUT);
    int b  = (int)(m / LOUT);
    int ic = kk / 3, kh = kk % 3;
    int t = 2 * lo - 1 + kh;
    float val = 0.f;
    if (t >= 0 && t < LL) val = x[((size_t)(b * LL + t)) * DD + ic];
    c[i] = __float2half_rn(val);
}

// ================= single-pass fp16 HMMA GEMM =================
// C[M,N] = A[M,K] @ B[N,K]^T, fp32 accum.
// CTA tile 128x128, BK=32, 8 warps (4M x 2N), cp.async double buffered.
#define EPI_NONE       0
#define EPI_BIAS       1
#define EPI_GELU_H     2
#define EPI_BIAS_RES   3

#define ROWB 80                // padded row: 32 fp16 + 8 pad = 80 bytes
#define MATB (128*ROWB)        // 10240 bytes per matrix buffer
#define STAGEB (2*MATB)        // A, B
#define SMEM_SZ (2*STAGEB)     // 40960

template <int EPI>
__global__ void __launch_bounds__(256) gemm_tc(
    const __half* __restrict__ Am, const __half* __restrict__ Bm,
    const float* __restrict__ bias, const float* __restrict__ res,
    float* __restrict__ C, __half* __restrict__ Oh,
    int M, int N, int K)
{
    extern __shared__ char smem[];
    uint32_t sb = smem_u32(smem);
    int tid = threadIdx.x;
    int warp = tid >> 5, lane = tid & 31;
    int warp_m = warp >> 1, warp_n = warp & 1;
    int m0 = blockIdx.y << 7, n0 = blockIdx.x << 7;

    float acc[2][8][4];
    #pragma unroll
    for (int i = 0; i < 2; i++)
        #pragma unroll
        for (int j = 0; j < 8; j++)
            #pragma unroll
            for (int k = 0; k < 4; k++) acc[i][j][k] = 0.f;

    int r0c = tid >> 2, kc0 = (tid & 3) * 8;
    int r1c = r0c + 64;

    int a_row = warp_m * 32 + (lane & 7) + ((lane >> 3) & 1) * 8;
    int a_k   = (lane >> 4) * 8;
    int b_n   = warp_n * 64 + (lane & 7) + (lane >> 4) * 8;
    int b_k   = ((lane >> 3) & 1) * 8;

    int nk = K >> 5;
    #define LOAD_STAGE(st, k0) do { \
        uint32_t base_ = sb + (st) * STAGEB; \
        uint32_t s0_ = base_ + r0c * ROWB + kc0 * 2; \
        uint32_t s1_ = base_ + r1c * ROWB + kc0 * 2; \
        size_t gA0_ = (size_t)(m0 + r0c) * K + (k0) + kc0; \
        size_t gA1_ = (size_t)(m0 + r1c) * K + (k0) + kc0; \
        size_t gB0_ = (size_t)(n0 + r0c) * K + (k0) + kc0; \
        size_t gB1_ = (size_t)(n0 + r1c) * K + (k0) + kc0; \
        cp16(s0_,        Am + gA0_); cp16(s1_,        Am + gA1_); \
        cp16(s0_ + MATB, Bm + gB0_); cp16(s1_ + MATB, Bm + gB1_); \
        CP_COMMIT(); \
    } while (0)

    LOAD_STAGE(0, 0);

    for (int kt = 0; kt < nk; kt++) {
        if (kt + 1 < nk) { LOAD_STAGE((kt + 1) & 1, (kt + 1) * 32); CP_WAIT(1); }
        else             { CP_WAIT(0); }
        __syncthreads();

        uint32_t base = sb + (kt & 1) * STAGEB;
        #pragma unroll
        for (int ks = 0; ks < 2; ks++) {
            int k = ks * 16;
            uint32_t ah[2][4];
            #pragma unroll
            for (int mt = 0; mt < 2; mt++) {
                uint32_t eo = base + (uint32_t)(a_row + mt * 16) * ROWB + (uint32_t)(k + a_k) * 2;
                ldsm4(ah[mt], eo);
            }
            #pragma unroll
            for (int p = 0; p < 4; p++) {
                uint32_t eo = base + MATB + (uint32_t)(b_n + p * 16) * ROWB + (uint32_t)(k + b_k) * 2;
                uint32_t b4[4];
                ldsm4(b4, eo);
                #pragma unroll
                for (int mt = 0; mt < 2; mt++) {
                    mma16816(acc[mt][2 * p],     ah[mt], b4[0], b4[1]);
                    mma16816(acc[mt][2 * p + 1], ah[mt], b4[2], b4[3]);
                }
            }
        }
        __syncthreads();
    }

    // epilogue
    int group = lane >> 2, tg = lane & 3;
    #pragma unroll
    for (int mt = 0; mt < 2; mt++) {
        #pragma unroll
        for (int half = 0; half < 2; half++) {
            int m = m0 + warp_m * 32 + mt * 16 + group + half * 8;
            #pragma unroll
            for (int nt = 0; nt < 8; nt++) {
                int n = n0 + warp_n * 64 + nt * 8 + tg * 2;
                float v0 = acc[mt][nt][half * 2 + 0];
                float v1 = acc[mt][nt][half * 2 + 1];
                if (EPI >= 1) { v0 += bias[n]; v1 += bias[n + 1]; }
                if (EPI == EPI_GELU_H) {
                    v0 = 0.5f * v0 * (1.0f + erff(v0 * 0.70710678118654752f));
                    v1 = 0.5f * v1 * (1.0f + erff(v1 * 0.70710678118654752f));
                    *(__half2*)&Oh[(size_t)m * N + n] =
                        __halves2half2(__float2half_rn(v0), __float2half_rn(v1));
                } else {
                    if (EPI == EPI_BIAS_RES) {
                        float2 rr = *(const float2*)&res[(size_t)m * N + n];
                        v0 += rr.x; v1 += rr.y;
                    }
                    *(float2*)&C[(size_t)m * N + n] = make_float2(v0, v1);
                }
            }
        }
    }
}

// ================= launch =================
extern "C" void kernel_launch(void* const* d_in, const int* in_sizes, int n_in,
                              void* d_out, int out_size)
{
    const float* x_in   = (const float*)d_in[0];
    const float* ln1_g  = (const float*)d_in[1];
    const float* ln1_b  = (const float*)d_in[2];
    const float* qkv_w  = (const float*)d_in[3];
    const float* qkv_b  = (const float*)d_in[4];
    const float* proj_w = (const float*)d_in[5];
    const float* proj_b = (const float*)d_in[6];
    const float* ln2_g  = (const float*)d_in[7];
    const float* ln2_b  = (const float*)d_in[8];
    const float* fc1_w  = (const float*)d_in[9];
    const float* fc1_b  = (const float*)d_in[10];
    const float* fc2_w  = (const float*)d_in[11];
    const float* fc2_b  = (const float*)d_in[12];
    const float* conv_w = (const float*)d_in[13];
    const float* dn_g   = (const float*)d_in[14];
    const float* dn_b   = (const float*)d_in[15];

    float* y_out = (float*)d_out;
    float* xbuf  = y_out + Y_ELEMS;

    void* p;
    #define GET(sym, var) cudaGetSymbolAddress(&p, sym); auto* var = (decltype(&sym[0]))p;
    GET(g_t0, t0) GET(g_qkv, qkv) GET(g_at, at) GET(g_hi, hi)
    GET(g_col, col) GET(g_conv, conv)
    GET(g_wq, wq) GET(g_wp, wp) GET(g_w1, w1) GET(g_w2, w2) GET(g_cw, cw)
    #undef GET

    cudaFuncSetAttribute(gemm_tc<EPI_NONE>,     cudaFuncAttributeMaxDynamicSharedMemorySize, SMEM_SZ);
    cudaFuncSetAttribute(gemm_tc<EPI_BIAS>,     cudaFuncAttributeMaxDynamicSharedMemorySize, SMEM_SZ);
    cudaFuncSetAttribute(gemm_tc<EPI_GELU_H>,   cudaFuncAttributeMaxDynamicSharedMemorySize, SMEM_SZ);
    cudaFuncSetAttribute(gemm_tc<EPI_BIAS_RES>, cudaFuncAttributeMaxDynamicSharedMemorySize, SMEM_SZ);

    prep_kernel<<<PREP_TOTAL / 256, 256>>>(qkv_w, proj_w, fc1_w, fc2_w, conv_w, wq, wp, w1, w2, cw);

    for (int i = 0; i < NDEPTH; i++) {
        const float* xin = (i == 0) ? x_in : xbuf;
        ln_h<<<NTOK, 256>>>(xin, ln1_g + i * DD, ln1_b + i * DD, t0);
        {   // qkv
            dim3 g(768 / 128, NTOK / 128);
            gemm_tc<EPI_BIAS><<<g, 256, SMEM_SZ>>>(t0, wq + (size_t)i * 768 * DD,
                qkv_b + i * 768, nullptr, qkv, nullptr, NTOK, 768, DD);
        }
        nat_attn_kernel<<<NTOK * HH / 8, 256>>>(qkv, at);
        {   // proj + residual
            dim3 g(DD / 128, NTOK / 128);
            gemm_tc<EPI_BIAS_RES><<<g, 256, SMEM_SZ>>>(at, wp + (size_t)i * DD * DD,
                proj_b + i * DD, xin, xbuf, nullptr, NTOK, DD, DD);
        }
        ln_h<<<NTOK, 256>>>(xbuf, ln2_g + i * DD, ln2_b + i * DD, t0);
        {   // fc1 + gelu -> fp16
            dim3 g(1024 / 128, NTOK / 128);
            gemm_tc<EPI_GELU_H><<<g, 256, SMEM_SZ>>>(t0, w1 + (size_t)i * 1024 * DD,
                fc1_b + i * 1024, nullptr, nullptr, hi, NTOK, 1024, DD);
        }
        {   // fc2 + residual
            dim3 g(DD / 128, NTOK / 128);
            gemm_tc<EPI_BIAS_RES><<<g, 256, SMEM_SZ>>>(hi, w2 + (size_t)i * DD * 1024,
                fc2_b + i * DD, xbuf, xbuf, nullptr, NTOK, DD, 1024);
        }
    }

    im2col_h<<<(BB * LOUT * KCONV + 255) / 256, 256>>>(xbuf, col);
    {
        dim3 g(OCH / 128, (BB * LOUT) / 128);
        gemm_tc<EPI_NONE><<<g, 256, SMEM_SZ>>>(col, cw,
            nullptr, nullptr, conv, nullptr, BB * LOUT, OCH, KCONV);
    }
    ln_plain<<<BB * LOUT, 256>>>(conv, dn_g, dn_b, y_out);
}

// round 6
// speedup vs baseline: 4.5869x; 1.0999x over previous
#include <cuda_runtime.h>
#include <cuda_fp16.h>
#include <cstdint>
#include <math.h>

#define BB 16
#define LL 2048
#define DD 256
#define HH 8
#define HDIM 32
#define KWIN 7
#define NDEPTH 2
#define LOUT 1024
#define OCH 512
#define KCONV 768
#define NTOK (BB*LL)
#define Y_ELEMS (BB*LOUT*OCH)
#define LPAD (LL+2)            // 2050 padded rows per batch for conv shadow

// ================= scratch =================
__device__ __half g_t0[(size_t)NTOK*DD];
__device__ __half g_qkvh[(size_t)NTOK*3*DD];
__device__ __half g_at[(size_t)NTOK*DD];
__device__ __half g_hi[(size_t)NTOK*4*DD];
__device__ __half g_xh2[(size_t)BB*LPAD*DD];    // padded fp16 shadow of x (for conv)
__device__ float  g_conv[(size_t)BB*LOUT*OCH];
// transposed fp16 weights [N][K]
__device__ __half g_wq[(size_t)NDEPTH*768*DD];
__device__ __half g_wp[(size_t)NDEPTH*DD*DD];
__device__ __half g_w1[(size_t)NDEPTH*1024*DD];
__device__ __half g_w2[(size_t)NDEPTH*DD*1024];
__device__ __half g_cw[(size_t)OCH*KCONV];      // kh-major K: k' = kh*256+ic

// ================= helpers =================
__device__ __forceinline__ uint32_t smem_u32(const void* p) {
    uint32_t a;
    asm("{ .reg .u64 t; cvta.to.shared.u64 t, %1; cvt.u32.u64 %0, t; }" : "=r"(a) : "l"(p));
    return a;
}
__device__ __forceinline__ void cp16(uint32_t s, const void* g) {
    asm volatile("cp.async.cg.shared.global [%0], [%1], 16;" :: "r"(s), "l"(g));
}
#define CP_COMMIT() asm volatile("cp.async.commit_group;" ::: "memory")
#define CP_WAIT(n)  asm volatile("cp.async.wait_group %0;" :: "n"(n) : "memory")

__device__ __forceinline__ void ldsm4(uint32_t* r, uint32_t addr) {
    asm volatile("ldmatrix.sync.aligned.m8n8.x4.shared.b16 {%0,%1,%2,%3}, [%4];"
        : "=r"(r[0]), "=r"(r[1]), "=r"(r[2]), "=r"(r[3]) : "r"(addr));
}
__device__ __forceinline__ void mma16816(float* c, const uint32_t* a, uint32_t b0, uint32_t b1) {
    asm volatile(
        "mma.sync.aligned.m16n8k16.row.col.f32.f16.f16.f32 "
        "{%0,%1,%2,%3}, {%4,%5,%6,%7}, {%8,%9}, {%0,%1,%2,%3};"
        : "+f"(c[0]), "+f"(c[1]), "+f"(c[2]), "+f"(c[3])
        : "r"(a[0]), "r"(a[1]), "r"(a[2]), "r"(a[3]), "r"(b0), "r"(b1));
}

__device__ __forceinline__ float blockReduceSum(float v) {
    __shared__ float s[8];
    int lane = threadIdx.x & 31, w = threadIdx.x >> 5;
    #pragma unroll
    for (int o = 16; o; o >>= 1) v += __shfl_xor_sync(0xffffffffu, v, o);
    if (lane == 0) s[w] = v;
    __syncthreads();
    if (w == 0) {
        v = (lane < 8) ? s[lane] : 0.0f;
        #pragma unroll
        for (int o = 4; o; o >>= 1) v += __shfl_xor_sync(0xffffffffu, v, o);
        if (lane == 0) s[0] = v;
    }
    __syncthreads();
    float r = s[0];
    __syncthreads();
    return r;
}

// ================= weight prep =================
#define S_WQ  (768*DD)
#define S_WP  (DD*DD)
#define S_W1  (1024*DD)
#define S_W2  (DD*1024)
#define LAYER_ELEMS (S_WQ + S_WP + S_W1 + S_W2)
#define PREP_TOTAL  (2*LAYER_ELEMS + OCH*KCONV)

__device__ __forceinline__ __half tr_h(const float* src, int j, int K, int N) {
    int n = j / K, kk = j % K;
    return __float2half_rn(src[(size_t)kk * N + n]);
}

__global__ void prep_kernel(const float* __restrict__ qkv_w, const float* __restrict__ proj_w,
                            const float* __restrict__ fc1_w, const float* __restrict__ fc2_w,
                            const float* __restrict__ conv_w,
                            __half* __restrict__ wq, __half* __restrict__ wp,
                            __half* __restrict__ w1, __half* __restrict__ w2,
                            __half* __restrict__ cw) {
    int i = blockIdx.x * blockDim.x + threadIdx.x;
    if (i >= PREP_TOTAL) return;
    if (i < 2 * LAYER_ELEMS) {
        int layer = i / LAYER_ELEMS;
        int j = i - layer * LAYER_ELEMS;
        if (j < S_WQ)
            wq[(size_t)layer * S_WQ + j] = tr_h(qkv_w + (size_t)layer * S_WQ, j, DD, 768);
        else if (j < S_WQ + S_WP)
            wp[(size_t)layer * S_WP + (j - S_WQ)] = tr_h(proj_w + (size_t)layer * S_WP, j - S_WQ, DD, DD);
        else if (j < S_WQ + S_WP + S_W1)
            w1[(size_t)layer * S_W1 + (j - S_WQ - S_WP)] = tr_h(fc1_w + (size_t)layer * S_W1, j - S_WQ - S_WP, DD, 1024);
        else
            w2[(size_t)layer * S_W2 + (j - S_WQ - S_WP - S_W1)] = tr_h(fc2_w + (size_t)layer * S_W2, j - S_WQ - S_WP - S_W1, 1024, DD);
    } else {
        // conv weight: [oc][ic*3+kh] -> cw[oc][kh*256+ic]
        int j = i - 2 * LAYER_ELEMS;
        int oc = j / KCONV, kp = j % KCONV;
        int kh = kp >> 8, ic = kp & 255;
        cw[j] = __float2half_rn(conv_w[(size_t)oc * KCONV + ic * 3 + kh]);
    }
}

// zero the pad rows (row 0 and row LPAD-1 of each batch) of xh2
__global__ void zeropad_kernel(__half* __restrict__ xh2) {
    int i = blockIdx.x * blockDim.x + threadIdx.x;
    if (i >= BB * 2 * DD) return;
    int b = i / (2 * DD);
    int r = (i / DD) & 1;
    int c = i & 255;
    xh2[((size_t)b * LPAD + (r ? (LPAD - 1) : 0)) * DD + c] = __float2half_rn(0.f);
}

// ================= elementwise kernels =================
__global__ void ln_h(const float* __restrict__ x, const float* __restrict__ g,
                     const float* __restrict__ bta, __half* __restrict__ o) {
    int row = blockIdx.x;
    const float* xr = x + (size_t)row * DD;
    float e = xr[threadIdx.x];
    float m = blockReduceSum(e) * (1.0f / DD);
    float d = e - m;
    float var = blockReduceSum(d * d) * (1.0f / DD);
    float r = rsqrtf(var + 1e-5f);
    float v = d * r * g[threadIdx.x] + bta[threadIdx.x];
    o[(size_t)row * DD + threadIdx.x] = __float2half_rn(v);
}

__global__ void ln_plain(const float* __restrict__ x, const float* __restrict__ g,
                         const float* __restrict__ bta, float* __restrict__ out) {
    int row = blockIdx.x;
    const float* xr = x + (size_t)row * OCH;
    float e0 = xr[threadIdx.x], e1 = xr[threadIdx.x + 256];
    float m = blockReduceSum(e0 + e1) * (1.0f / OCH);
    float d0 = e0 - m, d1 = e1 - m;
    float var = blockReduceSum(d0 * d0 + d1 * d1) * (1.0f / OCH);
    float r = rsqrtf(var + 1e-5f);
    float* orow = out + (size_t)row * OCH;
    orow[threadIdx.x]       = d0 * r * g[threadIdx.x] + bta[threadIdx.x];
    orow[threadIdx.x + 256] = d1 * r * g[threadIdx.x + 256] + bta[threadIdx.x + 256];
}

// Neighborhood attention: one THREAD per (token, head). No shuffles.
__global__ void __launch_bounds__(128) nat_attn_kernel(const __half* __restrict__ qkv,
                                                       __half* __restrict__ o) {
    int i = blockIdx.x * blockDim.x + threadIdx.x;
    int h = i & 7, token = i >> 3;
    int l = token & (LL - 1);
    int b = token >> 11;
    const float SCALE = 0.17677669529663687f;
    int start = l - (KWIN / 2);
    if (start < 0) start = 0;
    if (start > LL - KWIN) start = LL - KWIN;

    // load q: 32 halves = 4 uint4
    const __half* qp = qkv + (size_t)token * 768 + h * HDIM;
    __half2 qh[16];
    #pragma unroll
    for (int t = 0; t < 4; t++) {
        uint4 u = ((const uint4*)qp)[t];
        qh[t * 4 + 0] = *(__half2*)&u.x;
        qh[t * 4 + 1] = *(__half2*)&u.y;
        qh[t * 4 + 2] = *(__half2*)&u.z;
        qh[t * 4 + 3] = *(__half2*)&u.w;
    }

    // pass 1: scores
    const __half* kbase = qkv + (size_t)(b * LL + start) * 768 + 256 + h * HDIM;
    float s[KWIN];
    #pragma unroll
    for (int j = 0; j < KWIN; j++) {
        const uint4* kv = (const uint4*)(kbase + (size_t)j * 768);
        float acc = 0.f;
        #pragma unroll
        for (int t = 0; t < 4; t++) {
            uint4 u = kv[t];
            uint32_t w[4] = {u.x, u.y, u.z, u.w};
            #pragma unroll
            for (int c = 0; c < 4; c++) {
                float2 a = __half22float2(qh[t * 4 + c]);
                float2 kk = __half22float2(*(__half2*)&w[c]);
                acc += a.x * kk.x + a.y * kk.y;
            }
        }
        s[j] = acc * SCALE;
    }
    float mx = s[0];
    #pragma unroll
    for (int j = 1; j < KWIN; j++) mx = fmaxf(mx, s[j]);
    float sum = 0.f;
    #pragma unroll
    for (int j = 0; j < KWIN; j++) { s[j] = __expf(s[j] - mx); sum += s[j]; }
    float inv = 1.0f / sum;

    // pass 2: output accumulation
    const __half* vbase = kbase + 256;
    float2 acc[16];
    #pragma unroll
    for (int t = 0; t < 16; t++) acc[t] = make_float2(0.f, 0.f);
    #pragma unroll
    for (int j = 0; j < KWIN; j++) {
        float w = s[j];
        const uint4* vv = (const uint4*)(vbase + (size_t)j * 768);
        #pragma unroll
        for (int t = 0; t < 4; t++) {
            uint4 u = vv[t];
            uint32_t wd[4] = {u.x, u.y, u.z, u.w};
            #pragma unroll
            for (int c = 0; c < 4; c++) {
                float2 vf = __half22float2(*(__half2*)&wd[c]);
                acc[t * 4 + c].x += w * vf.x;
                acc[t * 4 + c].y += w * vf.y;
            }
        }
    }
    // store 32 halves
    __half* op = o + (size_t)token * DD + h * HDIM;
    #pragma unroll
    for (int t = 0; t < 4; t++) {
        uint4 u;
        uint32_t* wd = (uint32_t*)&u;
        #pragma unroll
        for (int c = 0; c < 4; c++) {
            __half2 hv = __floats2half2_rn(acc[t * 4 + c].x * inv, acc[t * 4 + c].y * inv);
            wd[c] = *(uint32_t*)&hv;
        }
        ((uint4*)op)[t] = u;
    }
}

// ================= single-pass fp16 HMMA GEMM =================
// C[M,N] = A[M,K] @ B[N,K]^T, fp32 accum.
// CTA tile 128x128, BK=32, 8 warps (4M x 2N), cp.async double buffered.
// ACONV=1: A addressed from padded conv shadow xh2 (kh-major K).
#define EPI_NONE        0
#define EPI_GELU_H      2
#define EPI_BIAS_RES    3
#define EPI_BIAS_H      4
#define EPI_BIAS_RES_SH 5

#define ROWB 80
#define MATB (128*ROWB)
#define STAGEB (2*MATB)
#define SMEM_SZ (2*STAGEB)     // 40960

template <int EPI, int ACONV>
__global__ void __launch_bounds__(256) gemm_tc(
    const __half* __restrict__ Am, const __half* __restrict__ Bm,
    const float* __restrict__ bias, const float* __restrict__ res,
    float* __restrict__ C, __half* __restrict__ Oh,
    int M, int N, int K)
{
    extern __shared__ char smem[];
    uint32_t sb = smem_u32(smem);
    int tid = threadIdx.x;
    int warp = tid >> 5, lane = tid & 31;
    int warp_m = warp >> 1, warp_n = warp & 1;
    int m0 = blockIdx.y << 7, n0 = blockIdx.x << 7;

    float acc[2][8][4];
    #pragma unroll
    for (int i = 0; i < 2; i++)
        #pragma unroll
        for (int j = 0; j < 8; j++)
            #pragma unroll
            for (int k = 0; k < 4; k++) acc[i][j][k] = 0.f;

    int r0c = tid >> 2, kc0 = (tid & 3) * 8;
    int r1c = r0c + 64;

    // conv-shadow addressing constants (M = b*1024 + lo)
    int lo0 = m0 & 1023;
    size_t abase = (size_t)(m0 >> 10) * LPAD * DD;

    int a_row = warp_m * 32 + (lane & 7) + ((lane >> 3) & 1) * 8;
    int a_k   = (lane >> 4) * 8;
    int b_n   = warp_n * 64 + (lane & 7) + (lane >> 4) * 8;
    int b_k   = ((lane >> 3) & 1) * 8;

    int nk = K >> 5;
    #define LOAD_STAGE(st, k0) do { \
        uint32_t base_ = sb + (st) * STAGEB; \
        uint32_t s0_ = base_ + r0c * ROWB + kc0 * 2; \
        uint32_t s1_ = base_ + r1c * ROWB + kc0 * 2; \
        size_t gB0_ = (size_t)(n0 + r0c) * K + (k0) + kc0; \
        size_t gB1_ = (size_t)(n0 + r1c) * K + (k0) + kc0; \
        size_t gA0_, gA1_; \
        if (ACONV) { \
            int kh_ = (k0) >> 8; int icb_ = ((k0) & 255) + kc0; \
            gA0_ = abase + (size_t)(2 * (lo0 + r0c) + kh_) * DD + icb_; \
            gA1_ = abase + (size_t)(2 * (lo0 + r1c) + kh_) * DD + icb_; \
        } else { \
            gA0_ = (size_t)(m0 + r0c) * K + (k0) + kc0; \
            gA1_ = (size_t)(m0 + r1c) * K + (k0) + kc0; \
        } \
        cp16(s0_,        Am + gA0_); cp16(s1_,        Am + gA1_); \
        cp16(s0_ + MATB, Bm + gB0_); cp16(s1_ + MATB, Bm + gB1_); \
        CP_COMMIT(); \
    } while (0)

    LOAD_STAGE(0, 0);

    for (int kt = 0; kt < nk; kt++) {
        if (kt + 1 < nk) { LOAD_STAGE((kt + 1) & 1, (kt + 1) * 32); CP_WAIT(1); }
        else             { CP_WAIT(0); }
        __syncthreads();

        uint32_t base = sb + (kt & 1) * STAGEB;
        #pragma unroll
        for (int ks = 0; ks < 2; ks++) {
            int k = ks * 16;
            uint32_t ah[2][4];
            #pragma unroll
            for (int mt = 0; mt < 2; mt++) {
                uint32_t eo = base + (uint32_t)(a_row + mt * 16) * ROWB + (uint32_t)(k + a_k) * 2;
                ldsm4(ah[mt], eo);
            }
            #pragma unroll
            for (int p = 0; p < 4; p++) {
                uint32_t eo = base + MATB + (uint32_t)(b_n + p * 16) * ROWB + (uint32_t)(k + b_k) * 2;
                uint32_t b4[4];
                ldsm4(b4, eo);
                #pragma unroll
                for (int mt = 0; mt < 2; mt++) {
                    mma16816(acc[mt][2 * p],     ah[mt], b4[0], b4[1]);
                    mma16816(acc[mt][2 * p + 1], ah[mt], b4[2], b4[3]);
                }
            }
        }
        __syncthreads();
    }

    // epilogue
    int group = lane >> 2, tg = lane & 3;
    #pragma unroll
    for (int mt = 0; mt < 2; mt++) {
        #pragma unroll
        for (int half = 0; half < 2; half++) {
            int m = m0 + warp_m * 32 + mt * 16 + group + half * 8;
            #pragma unroll
            for (int nt = 0; nt < 8; nt++) {
                int n = n0 + warp_n * 64 + nt * 8 + tg * 2;
                float v0 = acc[mt][nt][half * 2 + 0];
                float v1 = acc[mt][nt][half * 2 + 1];
                if (EPI != EPI_NONE) { v0 += bias[n]; v1 += bias[n + 1]; }
                if (EPI == EPI_GELU_H) {
                    v0 = 0.5f * v0 * (1.0f + erff(v0 * 0.70710678118654752f));
                    v1 = 0.5f * v1 * (1.0f + erff(v1 * 0.70710678118654752f));
                    *(__half2*)&Oh[(size_t)m * N + n] =
                        __halves2half2(__float2half_rn(v0), __float2half_rn(v1));
                } else if (EPI == EPI_BIAS_H) {
                    *(__half2*)&Oh[(size_t)m * N + n] =
                        __halves2half2(__float2half_rn(v0), __float2half_rn(v1));
                } else {
                    if (EPI == EPI_BIAS_RES || EPI == EPI_BIAS_RES_SH) {
                        float2 rr = *(const float2*)&res[(size_t)m * N + n];
                        v0 += rr.x; v1 += rr.y;
                    }
                    *(float2*)&C[(size_t)m * N + n] = make_float2(v0, v1);
                    if (EPI == EPI_BIAS_RES_SH) {
                        int b_ = m >> 11, t_ = m & (LL - 1);
                        size_t sh = ((size_t)b_ * LPAD + t_ + 1) * DD + n;
                        *(__half2*)&Oh[sh] =
                            __halves2half2(__float2half_rn(v0), __float2half_rn(v1));
                    }
                }
            }
        }
    }
}

// ================= launch =================
extern "C" void kernel_launch(void* const* d_in, const int* in_sizes, int n_in,
                              void* d_out, int out_size)
{
    const float* x_in   = (const float*)d_in[0];
    const float* ln1_g  = (const float*)d_in[1];
    const float* ln1_b  = (const float*)d_in[2];
    const float* qkv_w  = (const float*)d_in[3];
    const float* qkv_b  = (const float*)d_in[4];
    const float* proj_w = (const float*)d_in[5];
    const float* proj_b = (const float*)d_in[6];
    const float* ln2_g  = (const float*)d_in[7];
    const float* ln2_b  = (const float*)d_in[8];
    const float* fc1_w  = (const float*)d_in[9];
    const float* fc1_b  = (const float*)d_in[10];
    const float* fc2_w  = (const float*)d_in[11];
    const float* fc2_b  = (const float*)d_in[12];
    const float* conv_w = (const float*)d_in[13];
    const float* dn_g   = (const float*)d_in[14];
    const float* dn_b   = (const float*)d_in[15];

    float* y_out = (float*)d_out;
    float* xbuf  = y_out + Y_ELEMS;

    void* p;
    #define GET(sym, var) cudaGetSymbolAddress(&p, sym); auto* var = (decltype(&sym[0]))p;
    GET(g_t0, t0) GET(g_qkvh, qkvh) GET(g_at, at) GET(g_hi, hi)
    GET(g_xh2, xh2) GET(g_conv, conv)
    GET(g_wq, wq) GET(g_wp, wp) GET(g_w1, w1) GET(g_w2, w2) GET(g_cw, cw)
    #undef GET

    cudaFuncSetAttribute((const void*)gemm_tc<EPI_BIAS_H, 0>,      cudaFuncAttributeMaxDynamicSharedMemorySize, SMEM_SZ);
    cudaFuncSetAttribute((const void*)gemm_tc<EPI_BIAS_RES, 0>,    cudaFuncAttributeMaxDynamicSharedMemorySize, SMEM_SZ);
    cudaFuncSetAttribute((const void*)gemm_tc<EPI_GELU_H, 0>,      cudaFuncAttributeMaxDynamicSharedMemorySize, SMEM_SZ);
    cudaFuncSetAttribute((const void*)gemm_tc<EPI_BIAS_RES_SH, 0>, cudaFuncAttributeMaxDynamicSharedMemorySize, SMEM_SZ);
    cudaFuncSetAttribute((const void*)gemm_tc<EPI_NONE, 1>,        cudaFuncAttributeMaxDynamicSharedMemorySize, SMEM_SZ);

    prep_kernel<<<PREP_TOTAL / 256, 256>>>(qkv_w, proj_w, fc1_w, fc2_w, conv_w, wq, wp, w1, w2, cw);
    zeropad_kernel<<<(BB * 2 * DD + 255) / 256, 256>>>(xh2);

    for (int i = 0; i < NDEPTH; i++) {
        const float* xin = (i == 0) ? x_in : xbuf;
        ln_h<<<NTOK, 256>>>(xin, ln1_g + i * DD, ln1_b + i * DD, t0);
        {   // qkv -> fp16
            dim3 g(768 / 128, NTOK / 128);
            gemm_tc<EPI_BIAS_H, 0><<<g, 256, SMEM_SZ>>>(t0, wq + (size_t)i * 768 * DD,
                qkv_b + i * 768, nullptr, nullptr, qkvh, NTOK, 768, DD);
        }
        nat_attn_kernel<<<NTOK * HH / 128, 128>>>(qkvh, at);
        {   // proj + residual
            dim3 g(DD / 128, NTOK / 128);
            gemm_tc<EPI_BIAS_RES, 0><<<g, 256, SMEM_SZ>>>(at, wp + (size_t)i * DD * DD,
                proj_b + i * DD, xin, xbuf, nullptr, NTOK, DD, DD);
        }
        ln_h<<<NTOK, 256>>>(xbuf, ln2_g + i * DD, ln2_b + i * DD, t0);
        {   // fc1 + gelu -> fp16
            dim3 g(1024 / 128, NTOK / 128);
            gemm_tc<EPI_GELU_H, 0><<<g, 256, SMEM_SZ>>>(t0, w1 + (size_t)i * 1024 * DD,
                fc1_b + i * 1024, nullptr, nullptr, hi, NTOK, 1024, DD);
        }
        if (i < NDEPTH - 1) {   // fc2 + residual
            dim3 g(DD / 128, NTOK / 128);
            gemm_tc<EPI_BIAS_RES, 0><<<g, 256, SMEM_SZ>>>(hi, w2 + (size_t)i * DD * 1024,
                fc2_b + i * DD, xbuf, xbuf, nullptr, NTOK, DD, 1024);
        } else {                // last fc2: also write padded fp16 shadow for conv
            dim3 g(DD / 128, NTOK / 128);
            gemm_tc<EPI_BIAS_RES_SH, 0><<<g, 256, SMEM_SZ>>>(hi, w2 + (size_t)i * DD * 1024,
                fc2_b + i * DD, xbuf, xbuf, xh2, NTOK, DD, 1024);
        }
    }

    {   // conv GEMM reads shadow directly (no im2col)
        dim3 g(OCH / 128, (BB * LOUT) / 128);
        gemm_tc<EPI_NONE, 1><<<g, 256, SMEM_SZ>>>(xh2, cw,
            nullptr, nullptr, conv, nullptr, BB * LOUT, OCH, KCONV);
    }
    ln_plain<<<BB * LOUT, 256>>>(conv, dn_g, dn_b, y_out);
}

// round 7
// speedup vs baseline: 4.6224x; 1.0077x over previous
#include <cuda_runtime.h>
#include <cuda_fp16.h>
#include <cstdint>
#include <math.h>

#define BB 16
#define LL 2048
#define DD 256
#define HH 8
#define HDIM 32
#define KWIN 7
#define NDEPTH 2
#define LOUT 1024
#define OCH 512
#define KCONV 768
#define NTOK (BB*LL)
#define Y_ELEMS (BB*LOUT*OCH)
#define LPAD (LL+2)

// ================= scratch =================
__device__ __half g_t0[(size_t)NTOK*DD];
__device__ __half g_qkvh[(size_t)NTOK*3*DD];
__device__ __half g_at[(size_t)NTOK*DD];
__device__ __half g_hi[(size_t)NTOK*4*DD];
__device__ __half g_xh2[(size_t)BB*LPAD*DD];
__device__ float  g_conv[(size_t)BB*LOUT*OCH];
__device__ __half g_wq[(size_t)NDEPTH*768*DD];
__device__ __half g_wp[(size_t)NDEPTH*DD*DD];
__device__ __half g_w1[(size_t)NDEPTH*1024*DD];
__device__ __half g_w2[(size_t)NDEPTH*DD*1024];
__device__ __half g_cw[(size_t)OCH*KCONV];

// ================= helpers =================
__device__ __forceinline__ uint32_t smem_u32(const void* p) {
    uint32_t a;
    asm("{ .reg .u64 t; cvta.to.shared.u64 t, %1; cvt.u32.u64 %0, t; }" : "=r"(a) : "l"(p));
    return a;
}
__device__ __forceinline__ void cp16(uint32_t s, const void* g) {
    asm volatile("cp.async.cg.shared.global [%0], [%1], 16;" :: "r"(s), "l"(g));
}
#define CP_COMMIT() asm volatile("cp.async.commit_group;" ::: "memory")
#define CP_WAIT(n)  asm volatile("cp.async.wait_group %0;" :: "n"(n) : "memory")

__device__ __forceinline__ void ldsm4(uint32_t* r, uint32_t addr) {
    asm volatile("ldmatrix.sync.aligned.m8n8.x4.shared.b16 {%0,%1,%2,%3}, [%4];"
        : "=r"(r[0]), "=r"(r[1]), "=r"(r[2]), "=r"(r[3]) : "r"(addr));
}
__device__ __forceinline__ void mma16816(float* c, const uint32_t* a, uint32_t b0, uint32_t b1) {
    asm volatile(
        "mma.sync.aligned.m16n8k16.row.col.f32.f16.f16.f32 "
        "{%0,%1,%2,%3}, {%4,%5,%6,%7}, {%8,%9}, {%0,%1,%2,%3};"
        : "+f"(c[0]), "+f"(c[1]), "+f"(c[2]), "+f"(c[3])
        : "r"(a[0]), "r"(a[1]), "r"(a[2]), "r"(a[3]), "r"(b0), "r"(b1));
}

__device__ __forceinline__ float blockReduceSum(float v) {
    __shared__ float s[8];
    int lane = threadIdx.x & 31, w = threadIdx.x >> 5;
    #pragma unroll
    for (int o = 16; o; o >>= 1) v += __shfl_xor_sync(0xffffffffu, v, o);
    if (lane == 0) s[w] = v;
    __syncthreads();
    if (w == 0) {
        v = (lane < 8) ? s[lane] : 0.0f;
        #pragma unroll
        for (int o = 4; o; o >>= 1) v += __shfl_xor_sync(0xffffffffu, v, o);
        if (lane == 0) s[0] = v;
    }
    __syncthreads();
    float r = s[0];
    __syncthreads();
    return r;
}

// ================= weight prep =================
#define S_WQ  (768*DD)
#define S_WP  (DD*DD)
#define S_W1  (1024*DD)
#define S_W2  (DD*1024)
#define LAYER_ELEMS (S_WQ + S_WP + S_W1 + S_W2)
#define PREP_TOTAL  (2*LAYER_ELEMS + OCH*KCONV)

__device__ __forceinline__ __half tr_h(const float* src, int j, int K, int N) {
    int n = j / K, kk = j % K;
    return __float2half_rn(src[(size_t)kk * N + n]);
}

__global__ void prep_kernel(const float* __restrict__ qkv_w, const float* __restrict__ proj_w,
                            const float* __restrict__ fc1_w, const float* __restrict__ fc2_w,
                            const float* __restrict__ conv_w,
                            __half* __restrict__ wq, __half* __restrict__ wp,
                            __half* __restrict__ w1, __half* __restrict__ w2,
                            __half* __restrict__ cw) {
    int i = blockIdx.x * blockDim.x + threadIdx.x;
    if (i >= PREP_TOTAL) return;
    if (i < 2 * LAYER_ELEMS) {
        int layer = i / LAYER_ELEMS;
        int j = i - layer * LAYER_ELEMS;
        if (j < S_WQ)
            wq[(size_t)layer * S_WQ + j] = tr_h(qkv_w + (size_t)layer * S_WQ, j, DD, 768);
        else if (j < S_WQ + S_WP)
            wp[(size_t)layer * S_WP + (j - S_WQ)] = tr_h(proj_w + (size_t)layer * S_WP, j - S_WQ, DD, DD);
        else if (j < S_WQ + S_WP + S_W1)
            w1[(size_t)layer * S_W1 + (j - S_WQ - S_WP)] = tr_h(fc1_w + (size_t)layer * S_W1, j - S_WQ - S_WP, DD, 1024);
        else
            w2[(size_t)layer * S_W2 + (j - S_WQ - S_WP - S_W1)] = tr_h(fc2_w + (size_t)layer * S_W2, j - S_WQ - S_WP - S_W1, 1024, DD);
    } else {
        int j = i - 2 * LAYER_ELEMS;
        int oc = j / KCONV, kp = j % KCONV;
        int kh = kp >> 8, ic = kp & 255;
        cw[j] = __float2half_rn(conv_w[(size_t)oc * KCONV + ic * 3 + kh]);
    }
}

__global__ void zeropad_kernel(__half* __restrict__ xh2) {
    int i = blockIdx.x * blockDim.x + threadIdx.x;
    if (i >= BB * 2 * DD) return;
    int b = i / (2 * DD);
    int r = (i / DD) & 1;
    int c = i & 255;
    xh2[((size_t)b * LPAD + (r ? (LPAD - 1) : 0)) * DD + c] = __float2half_rn(0.f);
}

// ================= elementwise kernels =================
__global__ void ln_h(const float* __restrict__ x, const float* __restrict__ g,
                     const float* __restrict__ bta, __half* __restrict__ o) {
    int row = blockIdx.x;
    const float* xr = x + (size_t)row * DD;
    float e = xr[threadIdx.x];
    float m = blockReduceSum(e) * (1.0f / DD);
    float d = e - m;
    float var = blockReduceSum(d * d) * (1.0f / DD);
    float r = rsqrtf(var + 1e-5f);
    float v = d * r * g[threadIdx.x] + bta[threadIdx.x];
    o[(size_t)row * DD + threadIdx.x] = __float2half_rn(v);
}

__global__ void ln_plain(const float* __restrict__ x, const float* __restrict__ g,
                         const float* __restrict__ bta, float* __restrict__ out) {
    int row = blockIdx.x;
    const float* xr = x + (size_t)row * OCH;
    float e0 = xr[threadIdx.x], e1 = xr[threadIdx.x + 256];
    float m = blockReduceSum(e0 + e1) * (1.0f / OCH);
    float d0 = e0 - m, d1 = e1 - m;
    float var = blockReduceSum(d0 * d0 + d1 * d1) * (1.0f / OCH);
    float r = rsqrtf(var + 1e-5f);
    float* orow = out + (size_t)row * OCH;
    orow[threadIdx.x]       = d0 * r * g[threadIdx.x] + bta[threadIdx.x];
    orow[threadIdx.x + 256] = d1 * r * g[threadIdx.x + 256] + bta[threadIdx.x + 256];
}

// Neighborhood attention: one THREAD per (token, head). No shuffles.
__global__ void __launch_bounds__(128) nat_attn_kernel(const __half* __restrict__ qkv,
                                                       __half* __restrict__ o) {
    int i = blockIdx.x * blockDim.x + threadIdx.x;
    int h = i & 7, token = i >> 3;
    int l = token & (LL - 1);
    int b = token >> 11;
    const float SCALE = 0.17677669529663687f;
    int start = l - (KWIN / 2);
    if (start < 0) start = 0;
    if (start > LL - KWIN) start = LL - KWIN;

    const __half* qp = qkv + (size_t)token * 768 + h * HDIM;
    __half2 qh[16];
    #pragma unroll
    for (int t = 0; t < 4; t++) {
        uint4 u = ((const uint4*)qp)[t];
        qh[t * 4 + 0] = *(__half2*)&u.x;
        qh[t * 4 + 1] = *(__half2*)&u.y;
        qh[t * 4 + 2] = *(__half2*)&u.z;
        qh[t * 4 + 3] = *(__half2*)&u.w;
    }

    const __half* kbase = qkv + (size_t)(b * LL + start) * 768 + 256 + h * HDIM;
    float s[KWIN];
    #pragma unroll
    for (int j = 0; j < KWIN; j++) {
        const uint4* kv = (const uint4*)(kbase + (size_t)j * 768);
        float acc = 0.f;
        #pragma unroll
        for (int t = 0; t < 4; t++) {
            uint4 u = kv[t];
            uint32_t w[4] = {u.x, u.y, u.z, u.w};
            #pragma unroll
            for (int c = 0; c < 4; c++) {
                float2 a = __half22float2(qh[t * 4 + c]);
                float2 kk = __half22float2(*(__half2*)&w[c]);
                acc += a.x * kk.x + a.y * kk.y;
            }
        }
        s[j] = acc * SCALE;
    }
    float mx = s[0];
    #pragma unroll
    for (int j = 1; j < KWIN; j++) mx = fmaxf(mx, s[j]);
    float sum = 0.f;
    #pragma unroll
    for (int j = 0; j < KWIN; j++) { s[j] = __expf(s[j] - mx); sum += s[j]; }
    float inv = 1.0f / sum;

    const __half* vbase = kbase + 256;
    float2 acc[16];
    #pragma unroll
    for (int t = 0; t < 16; t++) acc[t] = make_float2(0.f, 0.f);
    #pragma unroll
    for (int j = 0; j < KWIN; j++) {
        float w = s[j];
        const uint4* vv = (const uint4*)(vbase + (size_t)j * 768);
        #pragma unroll
        for (int t = 0; t < 4; t++) {
            uint4 u = vv[t];
            uint32_t wd[4] = {u.x, u.y, u.z, u.w};
            #pragma unroll
            for (int c = 0; c < 4; c++) {
                float2 vf = __half22float2(*(__half2*)&wd[c]);
                acc[t * 4 + c].x += w * vf.x;
                acc[t * 4 + c].y += w * vf.y;
            }
        }
    }
    __half* op = o + (size_t)token * DD + h * HDIM;
    #pragma unroll
    for (int t = 0; t < 4; t++) {
        uint4 u;
        uint32_t* wd = (uint32_t*)&u;
        #pragma unroll
        for (int c = 0; c < 4; c++) {
            __half2 hv = __floats2half2_rn(acc[t * 4 + c].x * inv, acc[t * 4 + c].y * inv);
            wd[c] = *(uint32_t*)&hv;
        }
        ((uint4*)op)[t] = u;
    }
}

// ================= single-pass fp16 HMMA GEMM, 4-stage pipeline =================
#define EPI_NONE        0
#define EPI_GELU_H      2
#define EPI_BIAS_RES    3
#define EPI_BIAS_H      4
#define EPI_BIAS_RES_SH 5

#define ROWB 80
#define MATB (128*ROWB)
#define STAGEB (2*MATB)        // A, B per stage = 20480
#define NSTAGE 4
#define SMEM_SZ (NSTAGE*STAGEB) // 81920

template <int EPI, int ACONV>
__global__ void __launch_bounds__(256) gemm_tc(
    const __half* __restrict__ Am, const __half* __restrict__ Bm,
    const float* __restrict__ bias, const float* __restrict__ res,
    float* __restrict__ C, __half* __restrict__ Oh,
    int M, int N, int K)
{
    extern __shared__ char smem[];
    uint32_t sb = smem_u32(smem);
    int tid = threadIdx.x;
    int warp = tid >> 5, lane = tid & 31;
    int warp_m = warp >> 1, warp_n = warp & 1;
    int m0 = blockIdx.y << 7, n0 = blockIdx.x << 7;

    float acc[2][8][4];
    #pragma unroll
    for (int i = 0; i < 2; i++)
        #pragma unroll
        for (int j = 0; j < 8; j++)
            #pragma unroll
            for (int k = 0; k < 4; k++) acc[i][j][k] = 0.f;

    int r0c = tid >> 2, kc0 = (tid & 3) * 8;
    int r1c = r0c + 64;

    int lo0 = m0 & 1023;
    size_t abase = (size_t)(m0 >> 10) * LPAD * DD;

    int a_row = warp_m * 32 + (lane & 7) + ((lane >> 3) & 1) * 8;
    int a_k   = (lane >> 4) * 8;
    int b_n   = warp_n * 64 + (lane & 7) + (lane >> 4) * 8;
    int b_k   = ((lane >> 3) & 1) * 8;

    int nk = K >> 5;
    #define LOAD_STAGE(st, k0) do { \
        uint32_t base_ = sb + (st) * STAGEB; \
        uint32_t s0_ = base_ + r0c * ROWB + kc0 * 2; \
        uint32_t s1_ = base_ + r1c * ROWB + kc0 * 2; \
        size_t gB0_ = (size_t)(n0 + r0c) * K + (k0) + kc0; \
        size_t gB1_ = (size_t)(n0 + r1c) * K + (k0) + kc0; \
        size_t gA0_, gA1_; \
        if (ACONV) { \
            int kh_ = (k0) >> 8; int icb_ = ((k0) & 255) + kc0; \
            gA0_ = abase + (size_t)(2 * (lo0 + r0c) + kh_) * DD + icb_; \
            gA1_ = abase + (size_t)(2 * (lo0 + r1c) + kh_) * DD + icb_; \
        } else { \
            gA0_ = (size_t)(m0 + r0c) * K + (k0) + kc0; \
            gA1_ = (size_t)(m0 + r1c) * K + (k0) + kc0; \
        } \
        cp16(s0_,        Am + gA0_); cp16(s1_,        Am + gA1_); \
        cp16(s0_ + MATB, Bm + gB0_); cp16(s1_ + MATB, Bm + gB1_); \
        CP_COMMIT(); \
    } while (0)

    // prologue: fill NSTAGE-1 stages
    #pragma unroll
    for (int s = 0; s < NSTAGE - 1; s++) {
        if (s < nk) LOAD_STAGE(s, s * 32);
        else CP_COMMIT();
    }

    for (int kt = 0; kt < nk; kt++) {
        CP_WAIT(NSTAGE - 2);
        __syncthreads();
        {   // issue next load into the slot consumed last iteration
            int kn = kt + NSTAGE - 1;
            if (kn < nk) LOAD_STAGE(kn & (NSTAGE - 1), kn * 32);
            else CP_COMMIT();
        }
        uint32_t base = sb + (kt & (NSTAGE - 1)) * STAGEB;
        #pragma unroll
        for (int ks = 0; ks < 2; ks++) {
            int k = ks * 16;
            uint32_t ah[2][4];
            #pragma unroll
            for (int mt = 0; mt < 2; mt++) {
                uint32_t eo = base + (uint32_t)(a_row + mt * 16) * ROWB + (uint32_t)(k + a_k) * 2;
                ldsm4(ah[mt], eo);
            }
            #pragma unroll
            for (int p = 0; p < 4; p++) {
                uint32_t eo = base + MATB + (uint32_t)(b_n + p * 16) * ROWB + (uint32_t)(k + b_k) * 2;
                uint32_t b4[4];
                ldsm4(b4, eo);
                #pragma unroll
                for (int mt = 0; mt < 2; mt++) {
                    mma16816(acc[mt][2 * p],     ah[mt], b4[0], b4[1]);
                    mma16816(acc[mt][2 * p + 1], ah[mt], b4[2], b4[3]);
                }
            }
        }
    }

    // epilogue
    int group = lane >> 2, tg = lane & 3;
    #pragma unroll
    for (int mt = 0; mt < 2; mt++) {
        #pragma unroll
        for (int half = 0; half < 2; half++) {
            int m = m0 + warp_m * 32 + mt * 16 + group + half * 8;
            #pragma unroll
            for (int nt = 0; nt < 8; nt++) {
                int n = n0 + warp_n * 64 + nt * 8 + tg * 2;
                float v0 = acc[mt][nt][half * 2 + 0];
                float v1 = acc[mt][nt][half * 2 + 1];
                if (EPI != EPI_NONE) { v0 += bias[n]; v1 += bias[n + 1]; }
                if (EPI == EPI_GELU_H) {
                    v0 = 0.5f * v0 * (1.0f + erff(v0 * 0.70710678118654752f));
                    v1 = 0.5f * v1 * (1.0f + erff(v1 * 0.70710678118654752f));
                    *(__half2*)&Oh[(size_t)m * N + n] =
                        __halves2half2(__float2half_rn(v0), __float2half_rn(v1));
                } else if (EPI == EPI_BIAS_H) {
                    *(__half2*)&Oh[(size_t)m * N + n] =
                        __halves2half2(__float2half_rn(v0), __float2half_rn(v1));
                } else {
                    if (EPI == EPI_BIAS_RES || EPI == EPI_BIAS_RES_SH) {
                        float2 rr = *(const float2*)&res[(size_t)m * N + n];
                        v0 += rr.x; v1 += rr.y;
                    }
                    *(float2*)&C[(size_t)m * N + n] = make_float2(v0, v1);
                    if (EPI == EPI_BIAS_RES_SH) {
                        int b_ = m >> 11, t_ = m & (LL - 1);
                        size_t sh = ((size_t)b_ * LPAD + t_ + 1) * DD + n;
                        *(__half2*)&Oh[sh] =
                            __halves2half2(__float2half_rn(v0), __float2half_rn(v1));
                    }
                }
            }
        }
    }
}

// ================= launch =================
extern "C" void kernel_launch(void* const* d_in, const int* in_sizes, int n_in,
                              void* d_out, int out_size)
{
    const float* x_in   = (const float*)d_in[0];
    const float* ln1_g  = (const float*)d_in[1];
    const float* ln1_b  = (const float*)d_in[2];
    const float* qkv_w  = (const float*)d_in[3];
    const float* qkv_b  = (const float*)d_in[4];
    const float* proj_w = (const float*)d_in[5];
    const float* proj_b = (const float*)d_in[6];
    const float* ln2_g  = (const float*)d_in[7];
    const float* ln2_b  = (const float*)d_in[8];
    const float* fc1_w  = (const float*)d_in[9];
    const float* fc1_b  = (const float*)d_in[10];
    const float* fc2_w  = (const float*)d_in[11];
    const float* fc2_b  = (const float*)d_in[12];
    const float* conv_w = (const float*)d_in[13];
    const float* dn_g   = (const float*)d_in[14];
    const float* dn_b   = (const float*)d_in[15];

    float* y_out = (float*)d_out;
    float* xbuf  = y_out + Y_ELEMS;

    void* p;
    #define GET(sym, var) cudaGetSymbolAddress(&p, sym); auto* var = (decltype(&sym[0]))p;
    GET(g_t0, t0) GET(g_qkvh, qkvh) GET(g_at, at) GET(g_hi, hi)
    GET(g_xh2, xh2) GET(g_conv, conv)
    GET(g_wq, wq) GET(g_wp, wp) GET(g_w1, w1) GET(g_w2, w2) GET(g_cw, cw)
    #undef GET

    cudaFuncSetAttribute((const void*)gemm_tc<EPI_BIAS_H, 0>,      cudaFuncAttributeMaxDynamicSharedMemorySize, SMEM_SZ);
    cudaFuncSetAttribute((const void*)gemm_tc<EPI_BIAS_RES, 0>,    cudaFuncAttributeMaxDynamicSharedMemorySize, SMEM_SZ);
    cudaFuncSetAttribute((const void*)gemm_tc<EPI_GELU_H, 0>,      cudaFuncAttributeMaxDynamicSharedMemorySize, SMEM_SZ);
    cudaFuncSetAttribute((const void*)gemm_tc<EPI_BIAS_RES_SH, 0>, cudaFuncAttributeMaxDynamicSharedMemorySize, SMEM_SZ);
    cudaFuncSetAttribute((const void*)gemm_tc<EPI_NONE, 1>,        cudaFuncAttributeMaxDynamicSharedMemorySize, SMEM_SZ);

    prep_kernel<<<PREP_TOTAL / 256, 256>>>(qkv_w, proj_w, fc1_w, fc2_w, conv_w, wq, wp, w1, w2, cw);
    zeropad_kernel<<<(BB * 2 * DD + 255) / 256, 256>>>(xh2);

    for (int i = 0; i < NDEPTH; i++) {
        const float* xin = (i == 0) ? x_in : xbuf;
        ln_h<<<NTOK, 256>>>(xin, ln1_g + i * DD, ln1_b + i * DD, t0);
        {   // qkv -> fp16
            dim3 g(768 / 128, NTOK / 128);
            gemm_tc<EPI_BIAS_H, 0><<<g, 256, SMEM_SZ>>>(t0, wq + (size_t)i * 768 * DD,
                qkv_b + i * 768, nullptr, nullptr, qkvh, NTOK, 768, DD);
        }
        nat_attn_kernel<<<NTOK * HH / 128, 128>>>(qkvh, at);
        {   // proj + residual
            dim3 g(DD / 128, NTOK / 128);
            gemm_tc<EPI_BIAS_RES, 0><<<g, 256, SMEM_SZ>>>(at, wp + (size_t)i * DD * DD,
                proj_b + i * DD, xin, xbuf, nullptr, NTOK, DD, DD);
        }
        ln_h<<<NTOK, 256>>>(xbuf, ln2_g + i * DD, ln2_b + i * DD, t0);
        {   // fc1 + gelu -> fp16
            dim3 g(1024 / 128, NTOK / 128);
            gemm_tc<EPI_GELU_H, 0><<<g, 256, SMEM_SZ>>>(t0, w1 + (size_t)i * 1024 * DD,
                fc1_b + i * 1024, nullptr, nullptr, hi, NTOK, 1024, DD);
        }
        if (i < NDEPTH - 1) {
            dim3 g(DD / 128, NTOK / 128);
            gemm_tc<EPI_BIAS_RES, 0><<<g, 256, SMEM_SZ>>>(hi, w2 + (size_t)i * DD * 1024,
                fc2_b + i * DD, xbuf, xbuf, nullptr, NTOK, DD, 1024);
        } else {
            dim3 g(DD / 128, NTOK / 128);
            gemm_tc<EPI_BIAS_RES_SH, 0><<<g, 256, SMEM_SZ>>>(hi, w2 + (size_t)i * DD * 1024,
                fc2_b + i * DD, xbuf, xbuf, xh2, NTOK, DD, 1024);
        }
    }

    {   // conv GEMM reads shadow directly
        dim3 g(OCH / 128, (BB * LOUT) / 128);
        gemm_tc<EPI_NONE, 1><<<g, 256, SMEM_SZ>>>(xh2, cw,
            nullptr, nullptr, conv, nullptr, BB * LOUT, OCH, KCONV);
    }
    ln_plain<<<BB * LOUT, 256>>>(conv, dn_g, dn_b, y_out);
}